// round 13
// baseline (speedup 1.0000x reference)
#include <cuda_runtime.h>
#include <cuda_fp16.h>
#include <cstdint>

// QRU forward. R12:
//  - xk = x @ K_ih on legacy HMMA fp16 m16n8k16, SCALED 3-term split
//    (h + 2^-11 m^ + 2^-22 l^), 6 passes into 3 fp32 accumulator groups.
//    Split error ~2^-31 -> recurrence-amplified contribution ~1e-6 (negligible).
//  - main: R11 fused recurrent kernel (phase A = h_n@K_hh, K=64; combines and
//    gates fused via lane-quad shfl.bfly; 4 barriers/step).

__device__ float g_WHH[4 * 64 * 128];
__device__ float g_WB [4 * 128 * 128];
__device__ float g_bA[512];
__device__ float g_bB[512];
__device__ unsigned short g_B3[3ull * 512 * 256];      // K_ih^T fp16 h/m^/l^, signs folded
__device__ unsigned short g_X3[3ull * 131072 * 256];   // x fp16 h/m^/l^
__device__ float g_XK[131072ull * 512];                // x @ K_ih fp32

__constant__ int   c_M[16] = {0,1,2,3,  1,0,3,2,  2,3,0,1,  3,2,1,0};
__constant__ float c_S[16] = {1.f,-1.f,-1.f,-1.f,  1.f,1.f,-1.f,1.f,
                              1.f,1.f,1.f,-1.f,    1.f,-1.f,1.f,1.f};

#define SPLIT_S  4.8828125e-4f      // 2^-11
#define SPLIT_U  2048.f             // 2^11
#define SPLIT_U2 4194304.f          // 2^22

__device__ __forceinline__ void split3(float v, unsigned short& h,
                                       unsigned short& m, unsigned short& l)
{
    __half hh = __float2half_rn(v);
    float r1 = v - __half2float(hh);
    __half mm = __float2half_rn(r1 * SPLIT_U);
    float r2 = r1 - __half2float(mm) * SPLIT_S;
    __half ll = __float2half_rn(r2 * SPLIT_U2);
    h = __half_as_ushort(hh);
    m = __half_as_ushort(mm);
    l = __half_as_ushort(ll);
}

// ---------------- prep ------------------------------------------------------
__global__ void qru_prep(
    const float* __restrict__ wih_r, const float* __restrict__ wih_i,
    const float* __restrict__ wih_j, const float* __restrict__ wih_k,
    const float* __restrict__ whh_r, const float* __restrict__ whh_i,
    const float* __restrict__ whh_j, const float* __restrict__ whh_k,
    const float* __restrict__ wpc_r, const float* __restrict__ wpc_i,
    const float* __restrict__ wpc_j, const float* __restrict__ wpc_k,
    const float* __restrict__ wph_r, const float* __restrict__ wph_i,
    const float* __restrict__ wph_j, const float* __restrict__ wph_k,
    const float* __restrict__ b_ih, const float* __restrict__ b_hh,
    const float* __restrict__ b_ph, const float* __restrict__ b_pc)
{
    int i = blockIdx.x * blockDim.x + threadIdx.x;
    if (i < 65536) {
        int cc = i >> 14, k = (i >> 7) & 127, gg = i & 127;
        const float* src;
        if (k < 64) src = (cc == 0 ? wph_r : cc == 1 ? wph_i : cc == 2 ? wph_j : wph_k);
        else        src = (cc == 0 ? wpc_r : cc == 1 ? wpc_i : cc == 2 ? wpc_j : wpc_k);
        g_WB[i] = src[(k & 63) * 128 + gg];
    } else if (i < 98304) {
        int j = i - 65536;
        int cc = j >> 13, k = (j >> 7) & 63, gg = j & 127;
        const float* src = (cc == 0 ? whh_r : cc == 1 ? whh_i : cc == 2 ? whh_j : whh_k);
        g_WHH[j] = src[k * 128 + gg];
    } else if (i < 229376) {               // K_ih^T scaled fp16 3-term, signs folded
        int j = i - 98304;                 // j = n*256 + k
        int n = j >> 8, k = j & 255;
        int q = n >> 7, gg = n & 127, p = k >> 6, kq = k & 63;
        int cm = c_M[q * 4 + p];
        const float* src = (cm == 0 ? wih_r : cm == 1 ? wih_i : cm == 2 ? wih_j : wih_k);
        float val = c_S[q * 4 + p] * src[kq * 128 + gg];
        unsigned short h, m, l;
        split3(val, h, m, l);
        g_B3[j] = h;  g_B3[131072 + j] = m;  g_B3[262144 + j] = l;
    } else if (i < 230400) {
        int j = i - 229376;
        if (j < 512) g_bA[j] = b_ih[j] + b_hh[j];
        else         g_bB[j - 512] = b_ph[j - 512] + b_pc[j - 512];
    }
}

// ---------------- x split: g_X3 = scaled fp16 3-term of x -------------------
__global__ void __launch_bounds__(256, 4)
qru_xsplit(const float* __restrict__ x)
{
    int base = blockIdx.x * 256 + threadIdx.x;
#pragma unroll
    for (int i = 0; i < 4; ++i) {
        int idx = base + i * 2097152;               // 8192*256
        float4 a = ((const float4*)x)[idx];
        float v[4] = {a.x, a.y, a.z, a.w};
        unsigned short h[4], m[4], l[4];
#pragma unroll
        for (int e = 0; e < 4; ++e) split3(v[e], h[e], m[e], l[e]);
        uint2 ph, pm, pl;
        ph.x = (uint32_t)h[0] | ((uint32_t)h[1] << 16);
        ph.y = (uint32_t)h[2] | ((uint32_t)h[3] << 16);
        pm.x = (uint32_t)m[0] | ((uint32_t)m[1] << 16);
        pm.y = (uint32_t)m[2] | ((uint32_t)m[3] << 16);
        pl.x = (uint32_t)l[0] | ((uint32_t)l[1] << 16);
        pl.y = (uint32_t)l[2] | ((uint32_t)l[3] << 16);
        ((uint2*)(g_X3))[idx]            = ph;
        ((uint2*)(g_X3 + 33554432))[idx] = pm;
        ((uint2*)(g_X3 + 67108864))[idx] = pl;
    }
}

// ---------------- pre-GEMM: g_XK = x @ K_ih (fp16, 6 passes, 3 acc groups) --
#define MMAH(d, a, b0, b1)                                                     \
    asm volatile("mma.sync.aligned.m16n8k16.row.col.f32.f16.f16.f32 "          \
        "{%0,%1,%2,%3},{%4,%5,%6,%7},{%8,%9},{%0,%1,%2,%3};"                   \
        : "+f"((d)[0]), "+f"((d)[1]), "+f"((d)[2]), "+f"((d)[3])               \
        : "r"((a)[0]), "r"((a)[1]), "r"((a)[2]), "r"((a)[3]),                  \
          "r"(b0), "r"(b1))

__global__ void __launch_bounds__(512, 1)
qru_xk()
{
    extern __shared__ unsigned short smu[];
    // A terms: [128][72] at T*9216 (T=0,1,2); B terms: [64][72] at 27648+T*4608
    const int t = threadIdx.x;
    const int mt = blockIdx.x >> 3, nt = blockIdx.x & 7;
    const int lane = t & 31, w = t >> 5;
    const int wm = w >> 2, wn = w & 3;        // warp tile: 32m x 16n
    const int gq = lane >> 2, tg = lane & 3;

    float acc[3][2][2][4];                     // [group][mf][nf][4]
#pragma unroll
    for (int g = 0; g < 3; ++g)
#pragma unroll
        for (int f = 0; f < 2; ++f)
#pragma unroll
            for (int nf = 0; nf < 2; ++nf)
#pragma unroll
                for (int i = 0; i < 4; ++i) acc[g][f][nf][i] = 0.f;

    const int pa[6] = {0, 0, 1, 1, 0, 2};      // A term per pass
    const int pb[6] = {0, 1, 0, 1, 2, 0};      // B term per pass
    const int pg[6] = {0, 1, 1, 2, 2, 2};      // acc group per pass

    for (int kc = 0; kc < 4; ++kc) {
        // fills: A 3x128x8 chunks (3072), B 3x64x8 chunks (1536)
        for (int u = t; u < 4608; u += 512) {
            if (u < 3072) {
                int T = u >> 10, v = u & 1023, row = v >> 3, kx = v & 7;
                *(uint4*)(smu + T * 9216 + row * 72 + kx * 8) =
                    *(const uint4*)(g_X3 + (size_t)T * 33554432
                        + (size_t)(mt * 128 + row) * 256 + kc * 64 + kx * 8);
            } else {
                int v2 = u - 3072;
                int T = v2 >> 9, v = v2 & 511, n = v >> 3, kx = v & 7;
                *(uint4*)(smu + 27648 + T * 4608 + n * 72 + kx * 8) =
                    *(const uint4*)(g_B3 + (size_t)T * 131072
                        + (size_t)(nt * 64 + n) * 256 + kc * 64 + kx * 8);
            }
        }
        __syncthreads();

#pragma unroll
        for (int ps = 0; ps < 6; ++ps) {
            const unsigned short* As = smu + pa[ps] * 9216;
            const unsigned short* Bs = smu + 27648 + pb[ps] * 4608;
            float* ag0 = acc[pg[ps]][0][0];    // flat 16-float group view
#pragma unroll
            for (int ks = 0; ks < 4; ++ks) {
                const int k0 = ks * 16;
                uint32_t af[2][4];
#pragma unroll
                for (int f = 0; f < 2; ++f) {
                    const unsigned short* ap = As + (wm * 32 + f * 16 + gq) * 72 + k0 + 2 * tg;
                    af[f][0] = *(const uint32_t*)(ap);
                    af[f][1] = *(const uint32_t*)(ap + 8 * 72);
                    af[f][2] = *(const uint32_t*)(ap + 8);
                    af[f][3] = *(const uint32_t*)(ap + 8 * 72 + 8);
                }
#pragma unroll
                for (int nf = 0; nf < 2; ++nf) {
                    const unsigned short* bp = Bs + (wn * 16 + nf * 8 + gq) * 72 + k0 + 2 * tg;
                    uint32_t b0 = *(const uint32_t*)(bp);
                    uint32_t b1 = *(const uint32_t*)(bp + 8);
                    MMAH(ag0 + 0 * 8 + nf * 4, af[0], b0, b1);
                    MMAH(ag0 + 1 * 8 + nf * 4, af[1], b0, b1);
                }
            }
        }
        __syncthreads();
    }

#pragma unroll
    for (int f = 0; f < 2; ++f)
#pragma unroll
        for (int nf = 0; nf < 2; ++nf) {
            float v0[4];
#pragma unroll
            for (int i = 0; i < 4; ++i)
                v0[i] = acc[0][f][nf][i]
                      + SPLIT_S * (acc[1][f][nf][i] + SPLIT_S * acc[2][f][nf][i]);
            int row = mt * 128 + wm * 32 + f * 16 + gq;
            int col = nt * 64 + wn * 16 + nf * 8 + 2 * tg;
            *(float2*)&g_XK[(size_t)row * 512 + col]       = make_float2(v0[0], v0[1]);
            *(float2*)&g_XK[(size_t)(row + 8) * 512 + col] = make_float2(v0[2], v0[3]);
        }
}

// ---------------- recurrent kernel (R11 fused, math verified) ---------------
__device__ __forceinline__ void qdotA(const float* __restrict__ v,
                                      float* __restrict__ ds,
                                      int c, int ks, int r, int gv)
{
    float acc[4][4];
#pragma unroll
    for (int p = 0; p < 4; ++p)
#pragma unroll
        for (int i = 0; i < 4; ++i) acc[p][i] = 0.f;
    const float4* Wp = reinterpret_cast<const float4*>(g_WHH) + (c * 64 + ks * 32) * 32 + gv;
    const float* vb = v + r * 256 + ks * 32;
#pragma unroll 2
    for (int kb = 0; kb < 32; kb += 4) {
        float4 w0 = Wp[0], w1 = Wp[32], w2 = Wp[64], w3 = Wp[96];
        Wp += 128;
#pragma unroll
        for (int p = 0; p < 4; ++p) {
            const float4 vv = *reinterpret_cast<const float4*>(vb + p * 64 + kb);
            float* a = acc[p];
            a[0] = fmaf(vv.x, w0.x, a[0]); a[1] = fmaf(vv.x, w0.y, a[1]);
            a[2] = fmaf(vv.x, w0.z, a[2]); a[3] = fmaf(vv.x, w0.w, a[3]);
            a[0] = fmaf(vv.y, w1.x, a[0]); a[1] = fmaf(vv.y, w1.y, a[1]);
            a[2] = fmaf(vv.y, w1.z, a[2]); a[3] = fmaf(vv.y, w1.w, a[3]);
            a[0] = fmaf(vv.z, w2.x, a[0]); a[1] = fmaf(vv.z, w2.y, a[1]);
            a[2] = fmaf(vv.z, w2.z, a[2]); a[3] = fmaf(vv.z, w2.w, a[3]);
            a[0] = fmaf(vv.w, w3.x, a[0]); a[1] = fmaf(vv.w, w3.y, a[1]);
            a[2] = fmaf(vv.w, w3.z, a[2]); a[3] = fmaf(vv.w, w3.w, a[3]);
        }
    }
#pragma unroll
    for (int p = 0; p < 4; ++p)
        *reinterpret_cast<float4*>(ds + (p * 4 + c) * 512 + ks * 256 + r * 128 + gv * 4)
            = make_float4(acc[p][0], acc[p][1], acc[p][2], acc[p][3]);
}

__device__ __forceinline__ void qdotB(const float* __restrict__ v,
                                      float* __restrict__ ds,
                                      int c, int ks, int gv)
{
    float acc[4][2][4];
#pragma unroll
    for (int p = 0; p < 4; ++p)
#pragma unroll
        for (int r = 0; r < 2; ++r)
#pragma unroll
            for (int i = 0; i < 4; ++i) acc[p][r][i] = 0.f;
    const float4* Wp = reinterpret_cast<const float4*>(g_WB) + (c * 128 + ks * 32) * 32 + gv;
    const int k0 = ks * 32;
#pragma unroll 2
    for (int kb = 0; kb < 32; kb += 4) {
        float4 w0 = Wp[0], w1 = Wp[32], w2 = Wp[64], w3 = Wp[96];
        Wp += 128;
#pragma unroll
        for (int p = 0; p < 4; ++p)
#pragma unroll
            for (int r = 0; r < 2; ++r) {
                const float4 vv = *reinterpret_cast<const float4*>(v + (r * 4 + p) * 128 + k0 + kb);
                float* a = acc[p][r];
                a[0] = fmaf(vv.x, w0.x, a[0]); a[1] = fmaf(vv.x, w0.y, a[1]);
                a[2] = fmaf(vv.x, w0.z, a[2]); a[3] = fmaf(vv.x, w0.w, a[3]);
                a[0] = fmaf(vv.y, w1.x, a[0]); a[1] = fmaf(vv.y, w1.y, a[1]);
                a[2] = fmaf(vv.y, w1.z, a[2]); a[3] = fmaf(vv.y, w1.w, a[3]);
                a[0] = fmaf(vv.z, w2.x, a[0]); a[1] = fmaf(vv.z, w2.y, a[1]);
                a[2] = fmaf(vv.z, w2.z, a[2]); a[3] = fmaf(vv.z, w2.w, a[3]);
                a[0] = fmaf(vv.w, w3.x, a[0]); a[1] = fmaf(vv.w, w3.y, a[1]);
                a[2] = fmaf(vv.w, w3.z, a[2]); a[3] = fmaf(vv.w, w3.w, a[3]);
            }
    }
#pragma unroll
    for (int p = 0; p < 4; ++p)
#pragma unroll
        for (int r = 0; r < 2; ++r)
            *reinterpret_cast<float4*>(ds + (p * 4 + c) * 1024 + ks * 256 + r * 128 + gv * 4)
                = make_float4(acc[p][r][0], acc[p][r][1], acc[p][r][2], acc[p][r][3]);
}

__global__ void __launch_bounds__(512, 1)
qru_main(const float* __restrict__ hx,
         float* __restrict__ out, float* __restrict__ hT, int writeHT)
{
    extern __shared__ float smf[];
    float* ds = smf;
    float* vA = smf + 16384;
    float* vB = smf + 16896;

    const int t   = threadIdx.x;
    const int b0  = blockIdx.x * 2;
    const int cD  = t >> 7;
    const int ksA = (t >> 6) & 1;
    const int rA  = (t >> 5) & 1;
    const int gvA = t & 31;
    const int ksB = (t >> 5) & 3;
    const int gvB = t & 31;
    const int rC = t >> 8;
    const int nC = (t >> 2) & 63;
    const int cC = t & 3;

    float hcur = hx[(b0 + rC) * 256 + cC * 64 + nC];

    const float* xkbase = g_XK + (size_t)b0 * 512;
    const float bA0 = g_bA[cC * 128 + nC];
    const float bA1 = g_bA[cC * 128 + 64 + nC];
    const float bB0 = g_bB[cC * 128 + nC];
    const float bB1 = g_bB[cC * 128 + 64 + nC];
    const float wgt = (cC == 1) ? 2.f : ((cC == 3) ? 0.f : 1.f);
    int  sgn[4];
    float sgv[4];
#pragma unroll
    for (int p = 0; p < 4; ++p) { sgn[p] = c_M[cC * 4 + p]; sgv[p] = c_S[cC * 4 + p]; }

    for (int s = 0; s < 512; ++s) {
        const float* xkp = xkbase + (size_t)s * 256 * 512 + (size_t)rC * 512 + cC * 128 + nC;
        float xk0 = xkp[0];
        float xk1 = xkp[64];

        float m2 = hcur * hcur;
        m2 += __shfl_xor_sync(0xFFFFFFFFu, m2, 1);
        m2 += __shfl_xor_sync(0xFFFFFFFFu, m2, 2);
        float hn = hcur * (1.f / (sqrtf(m2) + 1e-4f));
        vA[rC * 256 + cC * 64 + nC] = hn;
        vB[(rC * 4 + cC) * 128 + nC] = hn;
        __syncthreads();

        qdotA(vA, ds, cD, ksA, rA, gvA);
        __syncthreads();

        float ya = xk0 + bA0;
        float yc = xk1 + bA1;
#pragma unroll
        for (int p = 0; p < 4; ++p) {
            const float* base = ds + (p * 4 + sgn[p]) * 512 + rC * 128;
            ya = fmaf(sgv[p], base[nC] + base[256 + nC], ya);
            yc = fmaf(sgv[p], base[64 + nC] + base[320 + nC], yc);
        }
        float as = ya * ya;
        as += __shfl_xor_sync(0xFFFFFFFFu, as, 1);
        as += __shfl_xor_sync(0xFFFFFFFFu, as, 2);
        float qv = yc * sqrtf(as);
        float qs = qv * qv;
        qs += __shfl_xor_sync(0xFFFFFFFFu, qs, 1);
        qs += __shfl_xor_sync(0xFFFFFFFFu, qs, 2);
        float ct = qv * (1.f / (sqrtf(qs) + 1e-4f));
        vB[(rC * 4 + cC) * 128 + 64 + nC] = ct;
        __syncthreads();

        qdotB(vB, ds, cD, ksB, gvB);
        __syncthreads();

        float yh = bB0;
        float yu = bB1;
#pragma unroll
        for (int p = 0; p < 4; ++p) {
            const float* base = ds + (p * 4 + sgn[p]) * 1024 + rC * 128;
            yh = fmaf(sgv[p], base[nC] + base[256 + nC] + base[512 + nC] + base[768 + nC], yh);
            yu = fmaf(sgv[p], base[64 + nC] + base[320 + nC] + base[576 + nC] + base[832 + nC], yu);
        }
        float hs = wgt * yh * yh;
        hs += __shfl_xor_sync(0xFFFFFFFFu, hs, 1);
        hs += __shfl_xor_sync(0xFFFFFFFFu, hs, 2);
        float cs = yu * yu;
        cs += __shfl_xor_sync(0xFFFFFFFFu, cs, 1);
        cs += __shfl_xor_sync(0xFFFFFFFFu, cs, 2);
        float av = fmaf(hn, sqrtf(hs), ct * sqrtf(cs));
        out[(size_t)(s * 256 + b0 + rC) * 256 + cC * 64 + nC] = av;
        hcur = av;
        if (writeHT && s == 511)
            hT[(size_t)(b0 + rC) * 256 + cC * 64 + nC] = av;
    }
}

extern "C" void kernel_launch(void* const* d_in, const int* in_sizes, int n_in,
                              void* d_out, int out_size)
{
    const float* x  = (const float*)d_in[0];
    const float* hx = (const float*)d_in[1];

    qru_prep<<<900, 256>>>(
        (const float*)d_in[2],  (const float*)d_in[3],  (const float*)d_in[4],  (const float*)d_in[5],
        (const float*)d_in[6],  (const float*)d_in[7],  (const float*)d_in[8],  (const float*)d_in[9],
        (const float*)d_in[10], (const float*)d_in[11], (const float*)d_in[12], (const float*)d_in[13],
        (const float*)d_in[14], (const float*)d_in[15], (const float*)d_in[16], (const float*)d_in[17],
        (const float*)d_in[18], (const float*)d_in[19], (const float*)d_in[20], (const float*)d_in[21]);

    qru_xsplit<<<8192, 256>>>(x);

    size_t smx = 41472 * sizeof(unsigned short);         // 82944 B
    cudaFuncSetAttribute(qru_xk, cudaFuncAttributeMaxDynamicSharedMemorySize, (int)smx);
    qru_xk<<<8192, 512, smx>>>();

    float* out = (float*)d_out;
    long long base = 512LL * 256 * 256;
    int writeHT = (out_size >= base + 256 * 256) ? 1 : 0;
    float* hT = out + base;

    size_t smm = (16384 + 512 + 1024) * sizeof(float);   // 71680 B
    cudaFuncSetAttribute(qru_main, cudaFuncAttributeMaxDynamicSharedMemorySize, (int)smm);
    qru_main<<<128, 512, smm>>>(hx, out, hT, writeHT);
}

// round 14
// speedup vs baseline: 1.1524x; 1.1524x over previous
#include <cuda_runtime.h>
#include <cuda_fp16.h>
#include <cstdint>

// QRU forward. R13:
//  - main: R9 unfused recurrent kernel (proven 3.66 ms, fp32).
//  - xk = x @ K_ih: fp16 HMMA, scaled 3-term split with TWO accumulator
//    groups (b-side pre-scaled m~/t terms), ldmatrix fragment loads,
//    32m x 32n warp tiles, in-kernel x split, 2 CTAs/SM.

__device__ float g_WHH[4 * 64 * 128];
__device__ float g_WB [4 * 128 * 128];
__device__ float g_bA[512];
__device__ float g_bB[512];
__device__ unsigned short g_B4[4ull * 512 * 256];   // K_ih^T fp16 h/m/m~/t, signs folded
__device__ float g_XK[131072ull * 512];

__constant__ int   c_M[16] = {0,1,2,3,  1,0,3,2,  2,3,0,1,  3,2,1,0};
__constant__ float c_S[16] = {1.f,-1.f,-1.f,-1.f,  1.f,1.f,-1.f,1.f,
                              1.f,1.f,1.f,-1.f,    1.f,-1.f,1.f,1.f};

#define SPLIT_S  4.8828125e-4f      // 2^-11
#define SPLIT_U  2048.f             // 2^11

// ---------------- prep ------------------------------------------------------
__global__ void qru_prep(
    const float* __restrict__ wih_r, const float* __restrict__ wih_i,
    const float* __restrict__ wih_j, const float* __restrict__ wih_k,
    const float* __restrict__ whh_r, const float* __restrict__ whh_i,
    const float* __restrict__ whh_j, const float* __restrict__ whh_k,
    const float* __restrict__ wpc_r, const float* __restrict__ wpc_i,
    const float* __restrict__ wpc_j, const float* __restrict__ wpc_k,
    const float* __restrict__ wph_r, const float* __restrict__ wph_i,
    const float* __restrict__ wph_j, const float* __restrict__ wph_k,
    const float* __restrict__ b_ih, const float* __restrict__ b_hh,
    const float* __restrict__ b_ph, const float* __restrict__ b_pc)
{
    int i = blockIdx.x * blockDim.x + threadIdx.x;
    if (i < 65536) {
        int cc = i >> 14, k = (i >> 7) & 127, gg = i & 127;
        const float* src;
        if (k < 64) src = (cc == 0 ? wph_r : cc == 1 ? wph_i : cc == 2 ? wph_j : wph_k);
        else        src = (cc == 0 ? wpc_r : cc == 1 ? wpc_i : cc == 2 ? wpc_j : wpc_k);
        g_WB[i] = src[(k & 63) * 128 + gg];
    } else if (i < 98304) {
        int j = i - 65536;
        int cc = j >> 13, k = (j >> 7) & 63, gg = j & 127;
        const float* src = (cc == 0 ? whh_r : cc == 1 ? whh_i : cc == 2 ? whh_j : whh_k);
        g_WHH[j] = src[k * 128 + gg];
    } else if (i < 229376) {               // K_ih^T 4-term scaled fp16, signs folded
        int j = i - 98304;                 // j = n*256 + k
        int n = j >> 8, k = j & 255;
        int q = n >> 7, gg = n & 127, p = k >> 6, kq = k & 63;
        int cm = c_M[q * 4 + p];
        const float* src = (cm == 0 ? wih_r : cm == 1 ? wih_i : cm == 2 ? wih_j : wih_k);
        float val = c_S[q * 4 + p] * src[kq * 128 + gg];
        __half hh = __float2half_rn(val);
        float r1 = val - __half2float(hh);
        __half mm = __float2half_rn(r1 * SPLIT_U);
        float r2 = r1 - __half2float(mm) * SPLIT_S;
        __half tt = __float2half_rn(r2 * SPLIT_U);
        __half mt = __float2half_rn(__half2float(mm) * SPLIT_S);
        g_B4[j]          = __half_as_ushort(hh);
        g_B4[131072 + j] = __half_as_ushort(mm);
        g_B4[262144 + j] = __half_as_ushort(mt);
        g_B4[393216 + j] = __half_as_ushort(tt);
    } else if (i < 230400) {
        int j = i - 229376;
        if (j < 512) g_bA[j] = b_ih[j] + b_hh[j];
        else         g_bB[j - 512] = b_ph[j - 512] + b_pc[j - 512];
    }
}

// ---------------- xk GEMM ---------------------------------------------------
__device__ __forceinline__ uint32_t s2u(const void* p) {
    uint32_t a;
    asm("{ .reg .u64 t; cvta.to.shared.u64 t, %1; cvt.u32.u64 %0, t; }" : "=r"(a) : "l"(p));
    return a;
}
#define MMAH(d, a, b0, b1)                                                     \
    asm volatile("mma.sync.aligned.m16n8k16.row.col.f32.f16.f16.f32 "          \
        "{%0,%1,%2,%3},{%4,%5,%6,%7},{%8,%9},{%0,%1,%2,%3};"                   \
        : "+f"((d)[0]), "+f"((d)[1]), "+f"((d)[2]), "+f"((d)[3])               \
        : "r"((a)[0]), "r"((a)[1]), "r"((a)[2]), "r"((a)[3]),                  \
          "r"(b0), "r"(b1))
#define LDSM4(r, addr)                                                         \
    asm volatile("ldmatrix.sync.aligned.m8n8.x4.shared.b16 {%0,%1,%2,%3}, [%4];" \
        : "=r"((r)[0]), "=r"((r)[1]), "=r"((r)[2]), "=r"((r)[3]) : "r"(addr))
#define LDSM2(r0, r1, addr)                                                    \
    asm volatile("ldmatrix.sync.aligned.m8n8.x2.shared.b16 {%0,%1}, [%2];"     \
        : "=r"(r0), "=r"(r1) : "r"(addr))

// SMEM (bytes): A terms h/m/t: [128][72]ush at T*18432 (T=0..2, 55296 total);
// B terms h/m/m~/t: [64][72]ush at 55296 + T*9216 (36864) -> 92160 B total.
__global__ void __launch_bounds__(256, 2)
qru_xk(const float* __restrict__ x)
{
    extern __shared__ unsigned short smu[];
    const uint32_t smb = s2u(smu);
    const int t = threadIdx.x;
    const int mt = blockIdx.x >> 3, nt = blockIdx.x & 7;
    const int n0 = nt * 64;
    const int lane = t & 31, w = t >> 5;
    const int wm = w >> 1, wn = w & 1;               // warp tile 32m x 32n
    const int gq = lane >> 2, tg = lane & 3;

    const uint32_t aRow = (uint32_t)((lane & 15) * 144 + (lane >> 4) * 16);
    const uint32_t bRow = (uint32_t)((lane & 7) * 144 + ((lane >> 3) & 1) * 16);

    float acc[2][2][4][4];                           // [group][mf][nf][4]
#pragma unroll
    for (int g = 0; g < 2; ++g)
#pragma unroll
        for (int f = 0; f < 2; ++f)
#pragma unroll
            for (int nf = 0; nf < 4; ++nf)
#pragma unroll
                for (int i = 0; i < 4; ++i) acc[g][f][nf][i] = 0.f;

    // passes: (ah,bh,G0) (ah,bm,G1) (am,bh,G1) (am,bm~,G1) (ah,bt,G1) (at,bh,G1)
    const int pa[6] = {0, 0, 1, 1, 0, 2};
    const int pb[6] = {0, 1, 0, 2, 3, 0};
    const int pg[6] = {0, 1, 1, 1, 1, 1};

    for (int kc = 0; kc < 4; ++kc) {
        // A fill + in-kernel scaled 3-term split: 128 rows x 16 float4
        for (int u = t; u < 2048; u += 256) {
            int row = u >> 4, q4 = u & 15;
            float4 a = ((const float4*)x)[(size_t)(mt * 128 + row) * 64 + kc * 16 + q4];
            float v[4] = {a.x, a.y, a.z, a.w};
            unsigned short H[4], M[4], T[4];
#pragma unroll
            for (int e = 0; e < 4; ++e) {
                __half hh = __float2half_rn(v[e]);
                float r1 = v[e] - __half2float(hh);
                __half mm = __float2half_rn(r1 * SPLIT_U);
                float r2 = r1 - __half2float(mm) * SPLIT_S;
                __half tt = __float2half_rn(r2 * SPLIT_U);
                H[e] = __half_as_ushort(hh);
                M[e] = __half_as_ushort(mm);
                T[e] = __half_as_ushort(tt);
            }
            uint32_t* pH = (uint32_t*)(smu + row * 72 + q4 * 4);
            uint32_t* pM = (uint32_t*)(smu + 9216 + row * 72 + q4 * 4);
            uint32_t* pT = (uint32_t*)(smu + 18432 + row * 72 + q4 * 4);
            pH[0] = (uint32_t)H[0] | ((uint32_t)H[1] << 16);
            pH[1] = (uint32_t)H[2] | ((uint32_t)H[3] << 16);
            pM[0] = (uint32_t)M[0] | ((uint32_t)M[1] << 16);
            pM[1] = (uint32_t)M[2] | ((uint32_t)M[3] << 16);
            pT[0] = (uint32_t)T[0] | ((uint32_t)T[1] << 16);
            pT[1] = (uint32_t)T[2] | ((uint32_t)T[3] << 16);
        }
        // B fill: 4 terms x 64 n x 8 x 16B
        for (int u = t; u < 2048; u += 256) {
            int T4 = u >> 9, v = u & 511, n = v >> 3, kx = v & 7;
            *(uint4*)(smu + 27648 + T4 * 4608 + n * 72 + kx * 8) =
                *(const uint4*)(g_B4 + (size_t)T4 * 131072
                                + (size_t)(n0 + n) * 256 + kc * 64 + kx * 8);
        }
        __syncthreads();

#pragma unroll
        for (int ps = 0; ps < 6; ++ps) {
            const uint32_t uA = smb + pa[ps] * 18432 + wm * 4608 + aRow;
            const uint32_t uB = smb + 55296 + pb[ps] * 9216 + wn * 4608 + bRow;
            float* g0 = &acc[pg[ps]][0][0][0];
            float* g1 = &acc[pg[ps]][1][0][0];
#pragma unroll
            for (int ks = 0; ks < 4; ++ks) {
                const uint32_t k0b = ks * 32;
                uint32_t af[4], ag[4];
                LDSM4(af, uA + k0b);                 // rows wm*32+0..15
                LDSM4(ag, uA + 2304 + k0b);          // rows wm*32+16..31
#pragma unroll
                for (int nf = 0; nf < 4; ++nf) {
                    uint32_t b0, b1;
                    LDSM2(b0, b1, uB + nf * 1152 + k0b);
                    MMAH(g0 + nf * 4, af, b0, b1);
                    MMAH(g1 + nf * 4, ag, b0, b1);
                }
            }
        }
        __syncthreads();
    }

#pragma unroll
    for (int f = 0; f < 2; ++f)
#pragma unroll
        for (int nf = 0; nf < 4; ++nf) {
            float v0[4];
#pragma unroll
            for (int i = 0; i < 4; ++i)
                v0[i] = acc[0][f][nf][i] + SPLIT_S * acc[1][f][nf][i];
            int row = mt * 128 + wm * 32 + f * 16 + gq;
            int col = n0 + wn * 32 + nf * 8 + 2 * tg;
            *(float2*)&g_XK[(size_t)row * 512 + col]       = make_float2(v0[0], v0[1]);
            *(float2*)&g_XK[(size_t)(row + 8) * 512 + col] = make_float2(v0[2], v0[3]);
        }
}

// ---------------- recurrent kernel (R9 verbatim — proven) -------------------
__device__ __forceinline__ void qdotA(const float* __restrict__ v,
                                      float* __restrict__ ds,
                                      int c, int ks, int r, int gv)
{
    float acc[4][4];
#pragma unroll
    for (int p = 0; p < 4; ++p)
#pragma unroll
        for (int i = 0; i < 4; ++i) acc[p][i] = 0.f;
    const float4* Wp = reinterpret_cast<const float4*>(g_WHH) + (c * 64 + ks * 32) * 32 + gv;
    const float* vb = v + r * 256 + ks * 32;
#pragma unroll 2
    for (int kb = 0; kb < 32; kb += 4) {
        float4 w0 = Wp[0], w1 = Wp[32], w2 = Wp[64], w3 = Wp[96];
        Wp += 128;
#pragma unroll
        for (int p = 0; p < 4; ++p) {
            const float4 vv = *reinterpret_cast<const float4*>(vb + p * 64 + kb);
            float* a = acc[p];
            a[0] = fmaf(vv.x, w0.x, a[0]); a[1] = fmaf(vv.x, w0.y, a[1]);
            a[2] = fmaf(vv.x, w0.z, a[2]); a[3] = fmaf(vv.x, w0.w, a[3]);
            a[0] = fmaf(vv.y, w1.x, a[0]); a[1] = fmaf(vv.y, w1.y, a[1]);
            a[2] = fmaf(vv.y, w1.z, a[2]); a[3] = fmaf(vv.y, w1.w, a[3]);
            a[0] = fmaf(vv.z, w2.x, a[0]); a[1] = fmaf(vv.z, w2.y, a[1]);
            a[2] = fmaf(vv.z, w2.z, a[2]); a[3] = fmaf(vv.z, w2.w, a[3]);
            a[0] = fmaf(vv.w, w3.x, a[0]); a[1] = fmaf(vv.w, w3.y, a[1]);
            a[2] = fmaf(vv.w, w3.z, a[2]); a[3] = fmaf(vv.w, w3.w, a[3]);
        }
    }
#pragma unroll
    for (int p = 0; p < 4; ++p)
        *reinterpret_cast<float4*>(ds + (p * 4 + c) * 512 + ks * 256 + r * 128 + gv * 4)
            = make_float4(acc[p][0], acc[p][1], acc[p][2], acc[p][3]);
}

__device__ __forceinline__ void qdotB(const float* __restrict__ v,
                                      float* __restrict__ ds,
                                      int c, int ks, int gv)
{
    float acc[4][2][4];
#pragma unroll
    for (int p = 0; p < 4; ++p)
#pragma unroll
        for (int r = 0; r < 2; ++r)
#pragma unroll
            for (int i = 0; i < 4; ++i) acc[p][r][i] = 0.f;
    const float4* Wp = reinterpret_cast<const float4*>(g_WB) + (c * 128 + ks * 32) * 32 + gv;
    const int k0 = ks * 32;
#pragma unroll 2
    for (int kb = 0; kb < 32; kb += 4) {
        float4 w0 = Wp[0], w1 = Wp[32], w2 = Wp[64], w3 = Wp[96];
        Wp += 128;
#pragma unroll
        for (int p = 0; p < 4; ++p)
#pragma unroll
            for (int r = 0; r < 2; ++r) {
                const float4 vv = *reinterpret_cast<const float4*>(v + (r * 4 + p) * 128 + k0 + kb);
                float* a = acc[p][r];
                a[0] = fmaf(vv.x, w0.x, a[0]); a[1] = fmaf(vv.x, w0.y, a[1]);
                a[2] = fmaf(vv.x, w0.z, a[2]); a[3] = fmaf(vv.x, w0.w, a[3]);
                a[0] = fmaf(vv.y, w1.x, a[0]); a[1] = fmaf(vv.y, w1.y, a[1]);
                a[2] = fmaf(vv.y, w1.z, a[2]); a[3] = fmaf(vv.y, w1.w, a[3]);
                a[0] = fmaf(vv.z, w2.x, a[0]); a[1] = fmaf(vv.z, w2.y, a[1]);
                a[2] = fmaf(vv.z, w2.z, a[2]); a[3] = fmaf(vv.z, w2.w, a[3]);
                a[0] = fmaf(vv.w, w3.x, a[0]); a[1] = fmaf(vv.w, w3.y, a[1]);
                a[2] = fmaf(vv.w, w3.z, a[2]); a[3] = fmaf(vv.w, w3.w, a[3]);
            }
    }
#pragma unroll
    for (int p = 0; p < 4; ++p)
#pragma unroll
        for (int r = 0; r < 2; ++r)
            *reinterpret_cast<float4*>(ds + (p * 4 + c) * 1024 + ks * 256 + r * 128 + gv * 4)
                = make_float4(acc[p][r][0], acc[p][r][1], acc[p][r][2], acc[p][r][3]);
}

__global__ void __launch_bounds__(512, 1)
qru_main(const float* __restrict__ hx,
         float* __restrict__ out, float* __restrict__ hT, int writeHT)
{
    extern __shared__ float smf[];
    float* ds = smf;
    float* vA = smf + 16384;
    float* vB = smf + 16896;
    float* yb = smf + 17920;
    float* hb = smf + 18944;

    const int t   = threadIdx.x;
    const int b0  = blockIdx.x * 2;
    const int c   = t >> 7;
    const int ksA = (t >> 6) & 1;
    const int rA  = (t >> 5) & 1;
    const int gvA = t & 31;
    const int ksB = (t >> 5) & 3;
    const int gvB = t & 31;
    const int g   = t & 127;
    const int rr  = t >> 8;
    const int idx = t & 255;

    hb[rr * 256 + idx] = hx[(b0 + rr) * 256 + idx];
    __syncthreads();

    const float* xk0p = g_XK + (size_t)b0 * 512 + t;

    for (int s = 0; s < 512; ++s) {
        const float* xkp = xk0p + (size_t)s * 256 * 512;
        float xk0 = xkp[0];
        float xk1 = xkp[512];

        if (t < 128) {
            const int r = t >> 6, n = t & 63;
            float h0 = hb[r * 256 + n],        h1 = hb[r * 256 + 64 + n];
            float h2 = hb[r * 256 + 128 + n],  h3 = hb[r * 256 + 192 + n];
            float inv = 1.f / (sqrtf(h0 * h0 + h1 * h1 + h2 * h2 + h3 * h3) + 1e-4f);
            h0 *= inv; h1 *= inv; h2 *= inv; h3 *= inv;
            vA[r * 256 + n]       = h0;  vA[r * 256 + 64 + n]  = h1;
            vA[r * 256 + 128 + n] = h2;  vA[r * 256 + 192 + n] = h3;
            vB[(r * 4 + 0) * 128 + n] = h0;  vB[(r * 4 + 1) * 128 + n] = h1;
            vB[(r * 4 + 2) * 128 + n] = h2;  vB[(r * 4 + 3) * 128 + n] = h3;
        }
        __syncthreads();

        qdotA(vA, ds, c, ksA, rA, gvA);
        __syncthreads();

        {
            float xk[2] = {xk0, xk1};
#pragma unroll
            for (int r = 0; r < 2; ++r) {
                float y = xk[r] + g_bA[c * 128 + g];
#pragma unroll
                for (int p = 0; p < 4; ++p) {
                    const int   cm = c_M[c * 4 + p];
                    const float sg = c_S[c * 4 + p];
                    const float* dp = ds + (p * 4 + cm) * 512 + r * 128 + g;
                    y = fmaf(sg, dp[0] + dp[256], y);
                }
                yb[r * 512 + c * 128 + g] = y;
            }
        }
        __syncthreads();

        if (t < 128) {
            const int r = t >> 6, n = t & 63;
            float a0 = yb[r * 512 + n],        a1 = yb[r * 512 + 128 + n];
            float a2 = yb[r * 512 + 256 + n],  a3 = yb[r * 512 + 384 + n];
            float ag = sqrtf(a0 * a0 + a1 * a1 + a2 * a2 + a3 * a3);
            float q0 = yb[r * 512 + 64 + n]  * ag;
            float q1 = yb[r * 512 + 192 + n] * ag;
            float q2 = yb[r * 512 + 320 + n] * ag;
            float q3 = yb[r * 512 + 448 + n] * ag;
            float inv = 1.f / (sqrtf(q0 * q0 + q1 * q1 + q2 * q2 + q3 * q3) + 1e-4f);
            vB[(r * 4 + 0) * 128 + 64 + n] = q0 * inv;
            vB[(r * 4 + 1) * 128 + 64 + n] = q1 * inv;
            vB[(r * 4 + 2) * 128 + 64 + n] = q2 * inv;
            vB[(r * 4 + 3) * 128 + 64 + n] = q3 * inv;
        }
        __syncthreads();

        qdotB(vB, ds, c, ksB, gvB);
        __syncthreads();

#pragma unroll
        for (int r = 0; r < 2; ++r) {
            float y = g_bB[c * 128 + g];
#pragma unroll
            for (int p = 0; p < 4; ++p) {
                const int   cm = c_M[c * 4 + p];
                const float sg = c_S[c * 4 + p];
                const float* dp = ds + (p * 4 + cm) * 1024 + r * 128 + g;
                y = fmaf(sg, dp[0] + dp[256] + dp[512] + dp[768], y);
            }
            yb[r * 512 + c * 128 + g] = y;
        }
        __syncthreads();

        if (t < 128) {
            const int r = t >> 6, n = t & 63;
            float u0 = yb[r * 512 + n];
            float u2 = yb[r * 512 + 128 + n];
            float u4 = yb[r * 512 + 256 + n];
            float gh = sqrtf(u0 * u0 + 2.f * u2 * u2 + u4 * u4);   // faithful gate
            float u1 = yb[r * 512 + 64 + n],  u3 = yb[r * 512 + 192 + n];
            float u5 = yb[r * 512 + 320 + n], u7 = yb[r * 512 + 448 + n];
            float gc = sqrtf(u1 * u1 + u3 * u3 + u5 * u5 + u7 * u7);
            float* orow = out + (size_t)(s * 256 + b0 + r) * 256;
#pragma unroll
            for (int p = 0; p < 4; ++p) {
                float hn = vB[(r * 4 + p) * 128 + n];
                float ct = vB[(r * 4 + p) * 128 + 64 + n];
                float av = fmaf(hn, gh, ct * gc);
                hb[r * 256 + p * 64 + n] = av;
                orow[p * 64 + n] = av;
            }
            if (writeHT && s == 511)
#pragma unroll
                for (int p = 0; p < 4; ++p)
                    hT[(size_t)(b0 + r) * 256 + p * 64 + n] = hb[r * 256 + p * 64 + n];
        }
    }
}

extern "C" void kernel_launch(void* const* d_in, const int* in_sizes, int n_in,
                              void* d_out, int out_size)
{
    const float* x  = (const float*)d_in[0];
    const float* hx = (const float*)d_in[1];

    qru_prep<<<900, 256>>>(
        (const float*)d_in[2],  (const float*)d_in[3],  (const float*)d_in[4],  (const float*)d_in[5],
        (const float*)d_in[6],  (const float*)d_in[7],  (const float*)d_in[8],  (const float*)d_in[9],
        (const float*)d_in[10], (const float*)d_in[11], (const float*)d_in[12], (const float*)d_in[13],
        (const float*)d_in[14], (const float*)d_in[15], (const float*)d_in[16], (const float*)d_in[17],
        (const float*)d_in[18], (const float*)d_in[19], (const float*)d_in[20], (const float*)d_in[21]);

    size_t smx = 92160;                                   // bytes
    cudaFuncSetAttribute(qru_xk, cudaFuncAttributeMaxDynamicSharedMemorySize, (int)smx);
    qru_xk<<<8192, 256, smx>>>(x);

    float* out = (float*)d_out;
    long long base = 512LL * 256 * 256;
    int writeHT = (out_size >= base + 256 * 256) ? 1 : 0;
    float* hT = out + base;

    size_t smm = (16384 + 512 + 1024 + 1024 + 512) * sizeof(float);  // 77824 B
    cudaFuncSetAttribute(qru_main, cudaFuncAttributeMaxDynamicSharedMemorySize, (int)smm);
    qru_main<<<128, 512, smm>>>(hx, out, hT, writeHT);
}

// round 15
// speedup vs baseline: 1.2585x; 1.0920x over previous
#include <cuda_runtime.h>
#include <cuda_fp16.h>
#include <cstdint>

// QRU forward. R14:
//  - xk pre-GEMM: R13 verbatim (fp16 HMMA scaled 3-term split, proven 2.1e-4).
//  - main: phase B via Gauss 12-product quaternion scheme (6 combo weight
//    matrices g_WB6, 8 x-combo slots), floor 8192->6144 cyc; g_WHH cached in
//    SMEM to keep L2 stream under the LTS cap; phase A unchanged.

__device__ float g_WHH[4 * 64 * 128];
__device__ float g_WB6[6 * 128 * 128];              // {W0,W1,W0+W1,W2,W3,W2+W3}
__device__ float g_bA[512];
__device__ float g_bB[512];
__device__ unsigned short g_B4[4ull * 512 * 256];   // K_ih^T fp16 h/m/m~/t, signs folded
__device__ float g_XK[131072ull * 512];

__constant__ int   c_M[16] = {0,1,2,3,  1,0,3,2,  2,3,0,1,  3,2,1,0};
__constant__ float c_S[16] = {1.f,-1.f,-1.f,-1.f,  1.f,1.f,-1.f,1.f,
                              1.f,1.f,1.f,-1.f,    1.f,-1.f,1.f,1.f};
// unit j (0..11) -> x-combo slot; unit j uses weight matrix (j % 6)
__constant__ int   c_SX[12] = {0,1,4,2,3,5,  2,3,6,0,1,7};

#define SPLIT_S  4.8828125e-4f      // 2^-11
#define SPLIT_U  2048.f             // 2^11

// ---------------- prep ------------------------------------------------------
__global__ void qru_prep(
    const float* __restrict__ wih_r, const float* __restrict__ wih_i,
    const float* __restrict__ wih_j, const float* __restrict__ wih_k,
    const float* __restrict__ whh_r, const float* __restrict__ whh_i,
    const float* __restrict__ whh_j, const float* __restrict__ whh_k,
    const float* __restrict__ wpc_r, const float* __restrict__ wpc_i,
    const float* __restrict__ wpc_j, const float* __restrict__ wpc_k,
    const float* __restrict__ wph_r, const float* __restrict__ wph_i,
    const float* __restrict__ wph_j, const float* __restrict__ wph_k,
    const float* __restrict__ b_ih, const float* __restrict__ b_hh,
    const float* __restrict__ b_ph, const float* __restrict__ b_pc)
{
    int i = blockIdx.x * blockDim.x + threadIdx.x;
    if (i < 98304) {                       // g_WB6: [mat][k][g]
        int mat = i >> 14, k = (i >> 7) & 127, gg = i & 127;
        const float* s0;
        const float* s1 = 0;
        int kk = (k & 63) * 128 + gg;
        if (k < 64) {
            s0 = (mat == 0 || mat == 2) ? wph_r :
                 (mat == 1)             ? wph_i :
                 (mat == 3 || mat == 5) ? wph_j : wph_k;
            if (mat == 2) s1 = wph_i;
            if (mat == 5) s1 = wph_k;
        } else {
            s0 = (mat == 0 || mat == 2) ? wpc_r :
                 (mat == 1)             ? wpc_i :
                 (mat == 3 || mat == 5) ? wpc_j : wpc_k;
            if (mat == 2) s1 = wpc_i;
            if (mat == 5) s1 = wpc_k;
        }
        float v = s0[kk];
        if (s1) v += s1[kk];
        g_WB6[i] = v;
    } else if (i < 131072) {               // g_WHH
        int j = i - 98304;
        int cc = j >> 13, k = (j >> 7) & 63, gg = j & 127;
        const float* src = (cc == 0 ? whh_r : cc == 1 ? whh_i : cc == 2 ? whh_j : whh_k);
        g_WHH[j] = src[k * 128 + gg];
    } else if (i < 262144) {               // g_B4: K_ih^T 4-term scaled fp16
        int j = i - 131072;                // j = n*256 + k
        int n = j >> 8, k = j & 255;
        int q = n >> 7, gg = n & 127, p = k >> 6, kq = k & 63;
        int cm = c_M[q * 4 + p];
        const float* src = (cm == 0 ? wih_r : cm == 1 ? wih_i : cm == 2 ? wih_j : wih_k);
        float val = c_S[q * 4 + p] * src[kq * 128 + gg];
        __half hh = __float2half_rn(val);
        float r1 = val - __half2float(hh);
        __half mm = __float2half_rn(r1 * SPLIT_U);
        float r2 = r1 - __half2float(mm) * SPLIT_S;
        __half tt = __float2half_rn(r2 * SPLIT_U);
        __half mt = __float2half_rn(__half2float(mm) * SPLIT_S);
        g_B4[j]          = __half_as_ushort(hh);
        g_B4[131072 + j] = __half_as_ushort(mm);
        g_B4[262144 + j] = __half_as_ushort(mt);
        g_B4[393216 + j] = __half_as_ushort(tt);
    } else if (i < 263168) {
        int j = i - 262144;
        if (j < 512) g_bA[j] = b_ih[j] + b_hh[j];
        else         g_bB[j - 512] = b_ph[j - 512] + b_pc[j - 512];
    }
}

// ---------------- xk GEMM (R13 verbatim, proven) ----------------------------
__device__ __forceinline__ uint32_t s2u(const void* p) {
    uint32_t a;
    asm("{ .reg .u64 t; cvta.to.shared.u64 t, %1; cvt.u32.u64 %0, t; }" : "=r"(a) : "l"(p));
    return a;
}
#define MMAH(d, a, b0, b1)                                                     \
    asm volatile("mma.sync.aligned.m16n8k16.row.col.f32.f16.f16.f32 "          \
        "{%0,%1,%2,%3},{%4,%5,%6,%7},{%8,%9},{%0,%1,%2,%3};"                   \
        : "+f"((d)[0]), "+f"((d)[1]), "+f"((d)[2]), "+f"((d)[3])               \
        : "r"((a)[0]), "r"((a)[1]), "r"((a)[2]), "r"((a)[3]),                  \
          "r"(b0), "r"(b1))
#define LDSM4(r, addr)                                                         \
    asm volatile("ldmatrix.sync.aligned.m8n8.x4.shared.b16 {%0,%1,%2,%3}, [%4];" \
        : "=r"((r)[0]), "=r"((r)[1]), "=r"((r)[2]), "=r"((r)[3]) : "r"(addr))
#define LDSM2(r0, r1, addr)                                                    \
    asm volatile("ldmatrix.sync.aligned.m8n8.x2.shared.b16 {%0,%1}, [%2];"     \
        : "=r"(r0), "=r"(r1) : "r"(addr))

__global__ void __launch_bounds__(256, 2)
qru_xk(const float* __restrict__ x)
{
    extern __shared__ unsigned short smu[];
    const uint32_t smb = s2u(smu);
    const int t = threadIdx.x;
    const int mt = blockIdx.x >> 3, nt = blockIdx.x & 7;
    const int n0 = nt * 64;
    const int lane = t & 31, w = t >> 5;
    const int wm = w >> 1, wn = w & 1;
    const int gq = lane >> 2, tg = lane & 3;

    const uint32_t aRow = (uint32_t)((lane & 15) * 144 + (lane >> 4) * 16);
    const uint32_t bRow = (uint32_t)((lane & 7) * 144 + ((lane >> 3) & 1) * 16);

    float acc[2][2][4][4];
#pragma unroll
    for (int g = 0; g < 2; ++g)
#pragma unroll
        for (int f = 0; f < 2; ++f)
#pragma unroll
            for (int nf = 0; nf < 4; ++nf)
#pragma unroll
                for (int i = 0; i < 4; ++i) acc[g][f][nf][i] = 0.f;

    const int pa[6] = {0, 0, 1, 1, 0, 2};
    const int pb[6] = {0, 1, 0, 2, 3, 0};
    const int pg[6] = {0, 1, 1, 1, 1, 1};

    for (int kc = 0; kc < 4; ++kc) {
        for (int u = t; u < 2048; u += 256) {
            int row = u >> 4, q4 = u & 15;
            float4 a = ((const float4*)x)[(size_t)(mt * 128 + row) * 64 + kc * 16 + q4];
            float v[4] = {a.x, a.y, a.z, a.w};
            unsigned short H[4], M[4], T[4];
#pragma unroll
            for (int e = 0; e < 4; ++e) {
                __half hh = __float2half_rn(v[e]);
                float r1 = v[e] - __half2float(hh);
                __half mm = __float2half_rn(r1 * SPLIT_U);
                float r2 = r1 - __half2float(mm) * SPLIT_S;
                __half tt = __float2half_rn(r2 * SPLIT_U);
                H[e] = __half_as_ushort(hh);
                M[e] = __half_as_ushort(mm);
                T[e] = __half_as_ushort(tt);
            }
            uint32_t* pH = (uint32_t*)(smu + row * 72 + q4 * 4);
            uint32_t* pM = (uint32_t*)(smu + 9216 + row * 72 + q4 * 4);
            uint32_t* pT = (uint32_t*)(smu + 18432 + row * 72 + q4 * 4);
            pH[0] = (uint32_t)H[0] | ((uint32_t)H[1] << 16);
            pH[1] = (uint32_t)H[2] | ((uint32_t)H[3] << 16);
            pM[0] = (uint32_t)M[0] | ((uint32_t)M[1] << 16);
            pM[1] = (uint32_t)M[2] | ((uint32_t)M[3] << 16);
            pT[0] = (uint32_t)T[0] | ((uint32_t)T[1] << 16);
            pT[1] = (uint32_t)T[2] | ((uint32_t)T[3] << 16);
        }
        for (int u = t; u < 2048; u += 256) {
            int T4 = u >> 9, v = u & 511, n = v >> 3, kx = v & 7;
            *(uint4*)(smu + 27648 + T4 * 4608 + n * 72 + kx * 8) =
                *(const uint4*)(g_B4 + (size_t)T4 * 131072
                                + (size_t)(n0 + n) * 256 + kc * 64 + kx * 8);
        }
        __syncthreads();

#pragma unroll
        for (int ps = 0; ps < 6; ++ps) {
            const uint32_t uA = smb + pa[ps] * 18432 + wm * 4608 + aRow;
            const uint32_t uB = smb + 55296 + pb[ps] * 9216 + wn * 4608 + bRow;
            float* g0 = &acc[pg[ps]][0][0][0];
            float* g1 = &acc[pg[ps]][1][0][0];
#pragma unroll
            for (int ks = 0; ks < 4; ++ks) {
                const uint32_t k0b = ks * 32;
                uint32_t af[4], ag[4];
                LDSM4(af, uA + k0b);
                LDSM4(ag, uA + 2304 + k0b);
#pragma unroll
                for (int nf = 0; nf < 4; ++nf) {
                    uint32_t b0, b1;
                    LDSM2(b0, b1, uB + nf * 1152 + k0b);
                    MMAH(g0 + nf * 4, af, b0, b1);
                    MMAH(g1 + nf * 4, ag, b0, b1);
                }
            }
        }
        __syncthreads();
    }

#pragma unroll
    for (int f = 0; f < 2; ++f)
#pragma unroll
        for (int nf = 0; nf < 4; ++nf) {
            float v0[4];
#pragma unroll
            for (int i = 0; i < 4; ++i)
                v0[i] = acc[0][f][nf][i] + SPLIT_S * acc[1][f][nf][i];
            int row = mt * 128 + wm * 32 + f * 16 + gq;
            int col = n0 + wn * 32 + nf * 8 + 2 * tg;
            *(float2*)&g_XK[(size_t)row * 512 + col]       = make_float2(v0[0], v0[1]);
            *(float2*)&g_XK[(size_t)(row + 8) * 512 + col] = make_float2(v0[2], v0[3]);
        }
}

// ---------------- recurrent kernel ------------------------------------------
// phase A dot (unchanged, W from SMEM)
__device__ __forceinline__ void qdotA(const float* __restrict__ Wsh,
                                      const float* __restrict__ v,
                                      float* __restrict__ ds,
                                      int c, int ks, int r, int gv)
{
    float acc[4][4];
#pragma unroll
    for (int p = 0; p < 4; ++p)
#pragma unroll
        for (int i = 0; i < 4; ++i) acc[p][i] = 0.f;
    const float4* Wp = reinterpret_cast<const float4*>(Wsh) + (c * 64 + ks * 32) * 32 + gv;
    const float* vb = v + r * 256 + ks * 32;
#pragma unroll 2
    for (int kb = 0; kb < 32; kb += 4) {
        float4 w0 = Wp[0], w1 = Wp[32], w2 = Wp[64], w3 = Wp[96];
        Wp += 128;
#pragma unroll
        for (int p = 0; p < 4; ++p) {
            const float4 vv = *reinterpret_cast<const float4*>(vb + p * 64 + kb);
            float* a = acc[p];
            a[0] = fmaf(vv.x, w0.x, a[0]); a[1] = fmaf(vv.x, w0.y, a[1]);
            a[2] = fmaf(vv.x, w0.z, a[2]); a[3] = fmaf(vv.x, w0.w, a[3]);
            a[0] = fmaf(vv.y, w1.x, a[0]); a[1] = fmaf(vv.y, w1.y, a[1]);
            a[2] = fmaf(vv.y, w1.z, a[2]); a[3] = fmaf(vv.y, w1.w, a[3]);
            a[0] = fmaf(vv.z, w2.x, a[0]); a[1] = fmaf(vv.z, w2.y, a[1]);
            a[2] = fmaf(vv.z, w2.z, a[2]); a[3] = fmaf(vv.z, w2.w, a[3]);
            a[0] = fmaf(vv.w, w3.x, a[0]); a[1] = fmaf(vv.w, w3.y, a[1]);
            a[2] = fmaf(vv.w, w3.z, a[2]); a[3] = fmaf(vv.w, w3.w, a[3]);
        }
    }
#pragma unroll
    for (int p = 0; p < 4; ++p)
        *reinterpret_cast<float4*>(ds + (p * 4 + c) * 512 + ks * 256 + r * 128 + gv * 4)
            = make_float4(acc[p][0], acc[p][1], acc[p][2], acc[p][3]);
}

// phase B dot, Gauss 12-product: warp = (wj in 6, ks in 2), units wj and wj+6
__device__ __forceinline__ void qdotB12(const float* __restrict__ vB,   // [r][slot][128]
                                        float* __restrict__ ds,
                                        int wj, int ks, int gv)
{
    const int s0 = c_SX[wj], s1 = c_SX[wj + 6];
    float acc[2][2][4];
#pragma unroll
    for (int u = 0; u < 2; ++u)
#pragma unroll
        for (int r = 0; r < 2; ++r)
#pragma unroll
            for (int i = 0; i < 4; ++i) acc[u][r][i] = 0.f;

    const float4* Wp = reinterpret_cast<const float4*>(g_WB6) + (wj * 128 + ks * 64) * 32 + gv;
    const float* v00 = vB + (0 * 8 + s0) * 128 + ks * 64;
    const float* v01 = vB + (1 * 8 + s0) * 128 + ks * 64;
    const float* v10 = vB + (0 * 8 + s1) * 128 + ks * 64;
    const float* v11 = vB + (1 * 8 + s1) * 128 + ks * 64;

#pragma unroll 2
    for (int kb = 0; kb < 64; kb += 4) {
        float4 w0 = Wp[0], w1 = Wp[32], w2 = Wp[64], w3 = Wp[96];
        Wp += 128;
#pragma unroll
        for (int st = 0; st < 4; ++st) {
            const float* vp = (st == 0) ? v00 : (st == 1) ? v01 : (st == 2) ? v10 : v11;
            const float4 vv = *reinterpret_cast<const float4*>(vp + kb);
            float* a = acc[st >> 1][st & 1];
            a[0] = fmaf(vv.x, w0.x, a[0]); a[1] = fmaf(vv.x, w0.y, a[1]);
            a[2] = fmaf(vv.x, w0.z, a[2]); a[3] = fmaf(vv.x, w0.w, a[3]);
            a[0] = fmaf(vv.y, w1.x, a[0]); a[1] = fmaf(vv.y, w1.y, a[1]);
            a[2] = fmaf(vv.y, w1.z, a[2]); a[3] = fmaf(vv.y, w1.w, a[3]);
            a[0] = fmaf(vv.z, w2.x, a[0]); a[1] = fmaf(vv.z, w2.y, a[1]);
            a[2] = fmaf(vv.z, w2.z, a[2]); a[3] = fmaf(vv.z, w2.w, a[3]);
            a[0] = fmaf(vv.w, w3.x, a[0]); a[1] = fmaf(vv.w, w3.y, a[1]);
            a[2] = fmaf(vv.w, w3.z, a[2]); a[3] = fmaf(vv.w, w3.w, a[3]);
        }
    }
#pragma unroll
    for (int u = 0; u < 2; ++u) {
        const int j = (u == 0) ? wj : wj + 6;
#pragma unroll
        for (int r = 0; r < 2; ++r)
            *reinterpret_cast<float4*>(ds + j * 512 + ks * 256 + r * 128 + gv * 4)
                = make_float4(acc[u][r][0], acc[u][r][1], acc[u][r][2], acc[u][r][3]);
    }
}

__global__ void __launch_bounds__(512, 1)
qru_main(const float* __restrict__ hx,
         float* __restrict__ out, float* __restrict__ hT, int writeHT)
{
    extern __shared__ float smf[];
    float* Wsh = smf;             // 32768 : g_WHH copy (128 KB)
    float* ds  = smf + 32768;     //  8192 : partials (A 8192 / B 6144)
    float* vA  = smf + 40960;     //   512
    float* vB  = smf + 41472;     //  2048 : [r][slot(8)][128]
    float* yb  = smf + 43520;     //  1024
    float* hb  = smf + 44544;     //   512

    const int t   = threadIdx.x;
    const int b0  = blockIdx.x * 2;
    const int c   = t >> 7;
    const int ksA = (t >> 6) & 1;
    const int rA  = (t >> 5) & 1;
    const int gvA = t & 31;
    const int w   = t >> 5;
    const int wjB = w >> 1;            // 0..7 (active < 6)
    const int ksB = w & 1;
    const int gvB = t & 31;
    const int g   = t & 127;
    const int rr  = t >> 8;
    const int idx = t & 255;

    for (int u = t; u < 32768; u += 512) Wsh[u] = g_WHH[u];
    hb[rr * 256 + idx] = hx[(b0 + rr) * 256 + idx];
    __syncthreads();

    const float* xk0p = g_XK + (size_t)b0 * 512 + t;

    for (int s = 0; s < 512; ++s) {
        const float* xkp = xk0p + (size_t)s * 256 * 512;
        float xk0 = xkp[0];
        float xk1 = xkp[512];

        // (a) normalize h -> vA (phase A) and vB h-half slots (phase B)
        if (t < 128) {
            const int r = t >> 6, n = t & 63;
            float h0 = hb[r * 256 + n],        h1 = hb[r * 256 + 64 + n];
            float h2 = hb[r * 256 + 128 + n],  h3 = hb[r * 256 + 192 + n];
            float inv = 1.f / (sqrtf(h0 * h0 + h1 * h1 + h2 * h2 + h3 * h3) + 1e-4f);
            h0 *= inv; h1 *= inv; h2 *= inv; h3 *= inv;
            vA[r * 256 + n]       = h0;  vA[r * 256 + 64 + n]  = h1;
            vA[r * 256 + 128 + n] = h2;  vA[r * 256 + 192 + n] = h3;
            float* vb = vB + r * 1024 + n;
            vb[0]   = h0;      vb[128] = h1;      vb[256] = h2;      vb[384] = h3;
            vb[512] = h0 + h1; vb[640] = h2 - h3; vb[768] = h2 + h3; vb[896] = h0 - h1;
        }
        __syncthreads();

        qdotA(Wsh, vA, ds, c, ksA, rA, gvA);
        __syncthreads();

        // combine A: ac = XK + bias + Hamilton(h_n @ W_hh)
        {
            float xk[2] = {xk0, xk1};
#pragma unroll
            for (int r = 0; r < 2; ++r) {
                float y = xk[r] + g_bA[c * 128 + g];
#pragma unroll
                for (int p = 0; p < 4; ++p) {
                    const int   cm = c_M[c * 4 + p];
                    const float sg = c_S[c * 4 + p];
                    const float* dp = ds + (p * 4 + cm) * 512 + r * 128 + g;
                    y = fmaf(sg, dp[0] + dp[256], y);
                }
                yb[r * 512 + c * 128 + g] = y;
            }
        }
        __syncthreads();

        // (e) amp gate + cand_t -> vB cand-half slots
        if (t < 128) {
            const int r = t >> 6, n = t & 63;
            float a0 = yb[r * 512 + n],        a1 = yb[r * 512 + 128 + n];
            float a2 = yb[r * 512 + 256 + n],  a3 = yb[r * 512 + 384 + n];
            float ag = sqrtf(a0 * a0 + a1 * a1 + a2 * a2 + a3 * a3);
            float q0 = yb[r * 512 + 64 + n]  * ag;
            float q1 = yb[r * 512 + 192 + n] * ag;
            float q2 = yb[r * 512 + 320 + n] * ag;
            float q3 = yb[r * 512 + 448 + n] * ag;
            float inv = 1.f / (sqrtf(q0 * q0 + q1 * q1 + q2 * q2 + q3 * q3) + 1e-4f);
            q0 *= inv; q1 *= inv; q2 *= inv; q3 *= inv;
            float* vb = vB + r * 1024 + 64 + n;
            vb[0]   = q0;      vb[128] = q1;      vb[256] = q2;      vb[384] = q3;
            vb[512] = q0 + q1; vb[640] = q2 - q3; vb[768] = q2 + q3; vb[896] = q0 - q1;
        }
        __syncthreads();

        if (w < 12) qdotB12(vB, ds, wjB, ksB, gvB);
        __syncthreads();

        // combine B (Gauss recombination):
        //   y0 = d0-d1-d3-d4            y1 = d2-d0-d1-d5+d3-d4
        //   y2 = d6-d7+d9+d10           y3 = d8-d6-d7+d11-d9+d10
#pragma unroll
        for (int r = 0; r < 2; ++r) {
            const float* dsr = ds + r * 128 + g;
#define DJ(j) (dsr[(j) * 512] + dsr[(j) * 512 + 256])
            float y = g_bB[c * 128 + g];
            if (c == 0)      y += DJ(0) - DJ(1) - DJ(3) - DJ(4);
            else if (c == 1) y += DJ(2) - DJ(0) - DJ(1) - DJ(5) + DJ(3) - DJ(4);
            else if (c == 2) y += DJ(6) - DJ(7) + DJ(9) + DJ(10);
            else             y += DJ(8) - DJ(6) - DJ(7) + DJ(11) - DJ(9) + DJ(10);
#undef DJ
            yb[r * 512 + c * 128 + g] = y;
        }
        __syncthreads();

        // (h) gates + new hidden + output
        if (t < 128) {
            const int r = t >> 6, n = t & 63;
            float u0 = yb[r * 512 + n];
            float u2 = yb[r * 512 + 128 + n];
            float u4 = yb[r * 512 + 256 + n];
            float gh = sqrtf(u0 * u0 + 2.f * u2 * u2 + u4 * u4);   // faithful gate
            float u1 = yb[r * 512 + 64 + n],  u3 = yb[r * 512 + 192 + n];
            float u5 = yb[r * 512 + 320 + n], u7 = yb[r * 512 + 448 + n];
            float gc = sqrtf(u1 * u1 + u3 * u3 + u5 * u5 + u7 * u7);
            float* orow = out + (size_t)(s * 256 + b0 + r) * 256;
#pragma unroll
            for (int p = 0; p < 4; ++p) {
                float hn = vB[r * 1024 + p * 128 + n];
                float ct = vB[r * 1024 + p * 128 + 64 + n];
                float av = fmaf(hn, gh, ct * gc);
                hb[r * 256 + p * 64 + n] = av;
                orow[p * 64 + n] = av;
            }
            if (writeHT && s == 511)
#pragma unroll
                for (int p = 0; p < 4; ++p)
                    hT[(size_t)(b0 + r) * 256 + p * 64 + n] = hb[r * 256 + p * 64 + n];
        }
    }
}

extern "C" void kernel_launch(void* const* d_in, const int* in_sizes, int n_in,
                              void* d_out, int out_size)
{
    const float* x  = (const float*)d_in[0];
    const float* hx = (const float*)d_in[1];

    qru_prep<<<1028, 256>>>(
        (const float*)d_in[2],  (const float*)d_in[3],  (const float*)d_in[4],  (const float*)d_in[5],
        (const float*)d_in[6],  (const float*)d_in[7],  (const float*)d_in[8],  (const float*)d_in[9],
        (const float*)d_in[10], (const float*)d_in[11], (const float*)d_in[12], (const float*)d_in[13],
        (const float*)d_in[14], (const float*)d_in[15], (const float*)d_in[16], (const float*)d_in[17],
        (const float*)d_in[18], (const float*)d_in[19], (const float*)d_in[20], (const float*)d_in[21]);

    size_t smx = 92160;
    cudaFuncSetAttribute(qru_xk, cudaFuncAttributeMaxDynamicSharedMemorySize, (int)smx);
    qru_xk<<<8192, 256, smx>>>(x);

    float* out = (float*)d_out;
    long long base = 512LL * 256 * 256;
    int writeHT = (out_size >= base + 256 * 256) ? 1 : 0;
    float* hT = out + base;

    size_t smm = 45056 * sizeof(float);                  // 180224 B
    cudaFuncSetAttribute(qru_main, cudaFuncAttributeMaxDynamicSharedMemorySize, (int)smm);
    qru_main<<<128, 512, smm>>>(hx, out, hT, writeHT);
}

// round 16
// speedup vs baseline: 1.2895x; 1.0246x over previous
#include <cuda_runtime.h>
#include <cuda_fp16.h>
#include <cstdint>

// QRU forward. R15:
//  - xk pre-GEMM: R13 verbatim (fp16 HMMA scaled 3-term split, ~1.02 ms).
//  - main: Gauss 12-product scheme for BOTH phases.
//      phase A: base W_hh (4 mats) in SMEM, 2 combo mats streamed from L2.
//      phase B: R14 verbatim (g_WB6 from L2).
//    h / h_n / cand_t register-carried in the t<128 threads; vA & hb deleted.
//    Floors: A 3072 + B 6144 = 9216 cyc/step.

__device__ float g_WHH[4 * 64 * 128];               // base A matrices [c][k][g]
__device__ float g_WA2[2 * 64 * 128];               // A combos {W0+W1, W2+W3}
__device__ float g_WB6[6 * 128 * 128];              // {W0,W1,W0+W1,W2,W3,W2+W3}
__device__ float g_bA[512];
__device__ float g_bB[512];
__device__ unsigned short g_B4[4ull * 512 * 256];   // K_ih^T fp16 h/m/m~/t, signs folded
__device__ float g_XK[131072ull * 512];

__constant__ int   c_M[16] = {0,1,2,3,  1,0,3,2,  2,3,0,1,  3,2,1,0};
__constant__ float c_S[16] = {1.f,-1.f,-1.f,-1.f,  1.f,1.f,-1.f,1.f,
                              1.f,1.f,1.f,-1.f,    1.f,-1.f,1.f,1.f};
// unit j (0..11) -> x-combo slot; unit j uses weight matrix (j % 6)
__constant__ int   c_SX[12] = {0,1,4,2,3,5,  2,3,6,0,1,7};

#define SPLIT_S  4.8828125e-4f      // 2^-11
#define SPLIT_U  2048.f             // 2^11

// ---------------- prep ------------------------------------------------------
__global__ void qru_prep(
    const float* __restrict__ wih_r, const float* __restrict__ wih_i,
    const float* __restrict__ wih_j, const float* __restrict__ wih_k,
    const float* __restrict__ whh_r, const float* __restrict__ whh_i,
    const float* __restrict__ whh_j, const float* __restrict__ whh_k,
    const float* __restrict__ wpc_r, const float* __restrict__ wpc_i,
    const float* __restrict__ wpc_j, const float* __restrict__ wpc_k,
    const float* __restrict__ wph_r, const float* __restrict__ wph_i,
    const float* __restrict__ wph_j, const float* __restrict__ wph_k,
    const float* __restrict__ b_ih, const float* __restrict__ b_hh,
    const float* __restrict__ b_ph, const float* __restrict__ b_pc)
{
    int i = blockIdx.x * blockDim.x + threadIdx.x;
    if (i < 98304) {                       // g_WB6: [mat][k][g]
        int mat = i >> 14, k = (i >> 7) & 127, gg = i & 127;
        const float* s0;
        const float* s1 = 0;
        int kk = (k & 63) * 128 + gg;
        if (k < 64) {
            s0 = (mat == 0 || mat == 2) ? wph_r :
                 (mat == 1)             ? wph_i :
                 (mat == 3 || mat == 5) ? wph_j : wph_k;
            if (mat == 2) s1 = wph_i;
            if (mat == 5) s1 = wph_k;
        } else {
            s0 = (mat == 0 || mat == 2) ? wpc_r :
                 (mat == 1)             ? wpc_i :
                 (mat == 3 || mat == 5) ? wpc_j : wpc_k;
            if (mat == 2) s1 = wpc_i;
            if (mat == 5) s1 = wpc_k;
        }
        float v = s0[kk];
        if (s1) v += s1[kk];
        g_WB6[i] = v;
    } else if (i < 131072) {               // g_WHH (base A)
        int j = i - 98304;
        int cc = j >> 13, k = (j >> 7) & 63, gg = j & 127;
        const float* src = (cc == 0 ? whh_r : cc == 1 ? whh_i : cc == 2 ? whh_j : whh_k);
        g_WHH[j] = src[k * 128 + gg];
    } else if (i < 147456) {               // g_WA2 combos
        int j = i - 131072;
        int m2 = j >> 13, k = (j >> 7) & 63, gg = j & 127;
        const float* a = m2 ? whh_j : whh_r;
        const float* b = m2 ? whh_k : whh_i;
        g_WA2[j] = a[k * 128 + gg] + b[k * 128 + gg];
    } else if (i < 278528) {               // g_B4: K_ih^T 4-term scaled fp16
        int j = i - 147456;                // j = n*256 + k
        int n = j >> 8, k = j & 255;
        int q = n >> 7, gg = n & 127, p = k >> 6, kq = k & 63;
        int cm = c_M[q * 4 + p];
        const float* src = (cm == 0 ? wih_r : cm == 1 ? wih_i : cm == 2 ? wih_j : wih_k);
        float val = c_S[q * 4 + p] * src[kq * 128 + gg];
        __half hh = __float2half_rn(val);
        float r1 = val - __half2float(hh);
        __half mm = __float2half_rn(r1 * SPLIT_U);
        float r2 = r1 - __half2float(mm) * SPLIT_S;
        __half tt = __float2half_rn(r2 * SPLIT_U);
        g_B4[j]          = __half_as_ushort(hh);
        g_B4[131072 + j] = __half_as_ushort(mm);
        g_B4[262144 + j] = __half_as_ushort(__float2half_rn(__half2float(mm) * SPLIT_S));
        g_B4[393216 + j] = __half_as_ushort(tt);
    } else if (i < 279552) {
        int j = i - 278528;
        if (j < 512) g_bA[j] = b_ih[j] + b_hh[j];
        else         g_bB[j - 512] = b_ph[j - 512] + b_pc[j - 512];
    }
}

// ---------------- xk GEMM (R13 verbatim, proven) ----------------------------
__device__ __forceinline__ uint32_t s2u(const void* p) {
    uint32_t a;
    asm("{ .reg .u64 t; cvta.to.shared.u64 t, %1; cvt.u32.u64 %0, t; }" : "=r"(a) : "l"(p));
    return a;
}
#define MMAH(d, a, b0, b1)                                                     \
    asm volatile("mma.sync.aligned.m16n8k16.row.col.f32.f16.f16.f32 "          \
        "{%0,%1,%2,%3},{%4,%5,%6,%7},{%8,%9},{%0,%1,%2,%3};"                   \
        : "+f"((d)[0]), "+f"((d)[1]), "+f"((d)[2]), "+f"((d)[3])               \
        : "r"((a)[0]), "r"((a)[1]), "r"((a)[2]), "r"((a)[3]),                  \
          "r"(b0), "r"(b1))
#define LDSM4(r, addr)                                                         \
    asm volatile("ldmatrix.sync.aligned.m8n8.x4.shared.b16 {%0,%1,%2,%3}, [%4];" \
        : "=r"((r)[0]), "=r"((r)[1]), "=r"((r)[2]), "=r"((r)[3]) : "r"(addr))
#define LDSM2(r0, r1, addr)                                                    \
    asm volatile("ldmatrix.sync.aligned.m8n8.x2.shared.b16 {%0,%1}, [%2];"     \
        : "=r"(r0), "=r"(r1) : "r"(addr))

__global__ void __launch_bounds__(256, 2)
qru_xk(const float* __restrict__ x)
{
    extern __shared__ unsigned short smu[];
    const uint32_t smb = s2u(smu);
    const int t = threadIdx.x;
    const int mt = blockIdx.x >> 3, nt = blockIdx.x & 7;
    const int n0 = nt * 64;
    const int lane = t & 31, w = t >> 5;
    const int wm = w >> 1, wn = w & 1;
    const int gq = lane >> 2, tg = lane & 3;

    const uint32_t aRow = (uint32_t)((lane & 15) * 144 + (lane >> 4) * 16);
    const uint32_t bRow = (uint32_t)((lane & 7) * 144 + ((lane >> 3) & 1) * 16);

    float acc[2][2][4][4];
#pragma unroll
    for (int g = 0; g < 2; ++g)
#pragma unroll
        for (int f = 0; f < 2; ++f)
#pragma unroll
            for (int nf = 0; nf < 4; ++nf)
#pragma unroll
                for (int i = 0; i < 4; ++i) acc[g][f][nf][i] = 0.f;

    const int pa[6] = {0, 0, 1, 1, 0, 2};
    const int pb[6] = {0, 1, 0, 2, 3, 0};
    const int pg[6] = {0, 1, 1, 1, 1, 1};

    for (int kc = 0; kc < 4; ++kc) {
        for (int u = t; u < 2048; u += 256) {
            int row = u >> 4, q4 = u & 15;
            float4 a = ((const float4*)x)[(size_t)(mt * 128 + row) * 64 + kc * 16 + q4];
            float v[4] = {a.x, a.y, a.z, a.w};
            unsigned short H[4], M[4], T[4];
#pragma unroll
            for (int e = 0; e < 4; ++e) {
                __half hh = __float2half_rn(v[e]);
                float r1 = v[e] - __half2float(hh);
                __half mm = __float2half_rn(r1 * SPLIT_U);
                float r2 = r1 - __half2float(mm) * SPLIT_S;
                __half tt = __float2half_rn(r2 * SPLIT_U);
                H[e] = __half_as_ushort(hh);
                M[e] = __half_as_ushort(mm);
                T[e] = __half_as_ushort(tt);
            }
            uint32_t* pH = (uint32_t*)(smu + row * 72 + q4 * 4);
            uint32_t* pM = (uint32_t*)(smu + 9216 + row * 72 + q4 * 4);
            uint32_t* pT = (uint32_t*)(smu + 18432 + row * 72 + q4 * 4);
            pH[0] = (uint32_t)H[0] | ((uint32_t)H[1] << 16);
            pH[1] = (uint32_t)H[2] | ((uint32_t)H[3] << 16);
            pM[0] = (uint32_t)M[0] | ((uint32_t)M[1] << 16);
            pM[1] = (uint32_t)M[2] | ((uint32_t)M[3] << 16);
            pT[0] = (uint32_t)T[0] | ((uint32_t)T[1] << 16);
            pT[1] = (uint32_t)T[2] | ((uint32_t)T[3] << 16);
        }
        for (int u = t; u < 2048; u += 256) {
            int T4 = u >> 9, v = u & 511, n = v >> 3, kx = v & 7;
            *(uint4*)(smu + 27648 + T4 * 4608 + n * 72 + kx * 8) =
                *(const uint4*)(g_B4 + (size_t)T4 * 131072
                                + (size_t)(n0 + n) * 256 + kc * 64 + kx * 8);
        }
        __syncthreads();

#pragma unroll
        for (int ps = 0; ps < 6; ++ps) {
            const uint32_t uA = smb + pa[ps] * 18432 + wm * 4608 + aRow;
            const uint32_t uB = smb + 55296 + pb[ps] * 9216 + wn * 4608 + bRow;
            float* g0 = &acc[pg[ps]][0][0][0];
            float* g1 = &acc[pg[ps]][1][0][0];
#pragma unroll
            for (int ks = 0; ks < 4; ++ks) {
                const uint32_t k0b = ks * 32;
                uint32_t af[4], ag[4];
                LDSM4(af, uA + k0b);
                LDSM4(ag, uA + 2304 + k0b);
#pragma unroll
                for (int nf = 0; nf < 4; ++nf) {
                    uint32_t b0, b1;
                    LDSM2(b0, b1, uB + nf * 1152 + k0b);
                    MMAH(g0 + nf * 4, af, b0, b1);
                    MMAH(g1 + nf * 4, ag, b0, b1);
                }
            }
        }
        __syncthreads();
    }

#pragma unroll
    for (int f = 0; f < 2; ++f)
#pragma unroll
        for (int nf = 0; nf < 4; ++nf) {
            float v0[4];
#pragma unroll
            for (int i = 0; i < 4; ++i)
                v0[i] = acc[0][f][nf][i] + SPLIT_S * acc[1][f][nf][i];
            int row = mt * 128 + wm * 32 + f * 16 + gq;
            int col = n0 + wn * 32 + nf * 8 + 2 * tg;
            *(float2*)&g_XK[(size_t)row * 512 + col]       = make_float2(v0[0], v0[1]);
            *(float2*)&g_XK[(size_t)(row + 8) * 512 + col] = make_float2(v0[2], v0[3]);
        }
}

// ---------------- recurrent kernel ------------------------------------------
// phase A Gauss dot: warp = (wj in 6, ks in 2); units wj, wj+6; K=64; W = one
// [64][128] matrix (SMEM for base mats, L2 for the two combos).
__device__ __forceinline__ void qdotA12(const float* __restrict__ W,
                                        const float* __restrict__ vB,
                                        float* __restrict__ ds,
                                        int wj, int ks, int gv)
{
    const int s0 = c_SX[wj], s1 = c_SX[wj + 6];
    float acc[2][2][4];
#pragma unroll
    for (int u = 0; u < 2; ++u)
#pragma unroll
        for (int r = 0; r < 2; ++r)
#pragma unroll
            for (int i = 0; i < 4; ++i) acc[u][r][i] = 0.f;

    const float4* Wp = reinterpret_cast<const float4*>(W) + (ks * 32) * 32 + gv;
    const float* v00 = vB + 0 * 1024 + s0 * 128 + ks * 32;   // h-half: offset 0..63
    const float* v01 = vB + 1 * 1024 + s0 * 128 + ks * 32;
    const float* v10 = vB + 0 * 1024 + s1 * 128 + ks * 32;
    const float* v11 = vB + 1 * 1024 + s1 * 128 + ks * 32;

#pragma unroll 2
    for (int kb = 0; kb < 32; kb += 4) {
        float4 w0 = Wp[0], w1 = Wp[32], w2 = Wp[64], w3 = Wp[96];
        Wp += 128;
#pragma unroll
        for (int st = 0; st < 4; ++st) {
            const float* vp = (st == 0) ? v00 : (st == 1) ? v01 : (st == 2) ? v10 : v11;
            const float4 vv = *reinterpret_cast<const float4*>(vp + kb);
            float* a = acc[st >> 1][st & 1];
            a[0] = fmaf(vv.x, w0.x, a[0]); a[1] = fmaf(vv.x, w0.y, a[1]);
            a[2] = fmaf(vv.x, w0.z, a[2]); a[3] = fmaf(vv.x, w0.w, a[3]);
            a[0] = fmaf(vv.y, w1.x, a[0]); a[1] = fmaf(vv.y, w1.y, a[1]);
            a[2] = fmaf(vv.y, w1.z, a[2]); a[3] = fmaf(vv.y, w1.w, a[3]);
            a[0] = fmaf(vv.z, w2.x, a[0]); a[1] = fmaf(vv.z, w2.y, a[1]);
            a[2] = fmaf(vv.z, w2.z, a[2]); a[3] = fmaf(vv.z, w2.w, a[3]);
            a[0] = fmaf(vv.w, w3.x, a[0]); a[1] = fmaf(vv.w, w3.y, a[1]);
            a[2] = fmaf(vv.w, w3.z, a[2]); a[3] = fmaf(vv.w, w3.w, a[3]);
        }
    }
#pragma unroll
    for (int u = 0; u < 2; ++u) {
        const int j = wj + u * 6;
#pragma unroll
        for (int r = 0; r < 2; ++r)
            *reinterpret_cast<float4*>(ds + j * 512 + ks * 256 + r * 128 + gv * 4)
                = make_float4(acc[u][r][0], acc[u][r][1], acc[u][r][2], acc[u][r][3]);
    }
}

// phase B Gauss dot (R14 verbatim): K=128, W from g_WB6 (L2)
__device__ __forceinline__ void qdotB12(const float* __restrict__ vB,
                                        float* __restrict__ ds,
                                        int wj, int ks, int gv)
{
    const int s0 = c_SX[wj], s1 = c_SX[wj + 6];
    float acc[2][2][4];
#pragma unroll
    for (int u = 0; u < 2; ++u)
#pragma unroll
        for (int r = 0; r < 2; ++r)
#pragma unroll
            for (int i = 0; i < 4; ++i) acc[u][r][i] = 0.f;

    const float4* Wp = reinterpret_cast<const float4*>(g_WB6) + (wj * 128 + ks * 64) * 32 + gv;
    const float* v00 = vB + 0 * 1024 + s0 * 128 + ks * 64;
    const float* v01 = vB + 1 * 1024 + s0 * 128 + ks * 64;
    const float* v10 = vB + 0 * 1024 + s1 * 128 + ks * 64;
    const float* v11 = vB + 1 * 1024 + s1 * 128 + ks * 64;

#pragma unroll 2
    for (int kb = 0; kb < 64; kb += 4) {
        float4 w0 = Wp[0], w1 = Wp[32], w2 = Wp[64], w3 = Wp[96];
        Wp += 128;
#pragma unroll
        for (int st = 0; st < 4; ++st) {
            const float* vp = (st == 0) ? v00 : (st == 1) ? v01 : (st == 2) ? v10 : v11;
            const float4 vv = *reinterpret_cast<const float4*>(vp + kb);
            float* a = acc[st >> 1][st & 1];
            a[0] = fmaf(vv.x, w0.x, a[0]); a[1] = fmaf(vv.x, w0.y, a[1]);
            a[2] = fmaf(vv.x, w0.z, a[2]); a[3] = fmaf(vv.x, w0.w, a[3]);
            a[0] = fmaf(vv.y, w1.x, a[0]); a[1] = fmaf(vv.y, w1.y, a[1]);
            a[2] = fmaf(vv.y, w1.z, a[2]); a[3] = fmaf(vv.y, w1.w, a[3]);
            a[0] = fmaf(vv.z, w2.x, a[0]); a[1] = fmaf(vv.z, w2.y, a[1]);
            a[2] = fmaf(vv.z, w2.z, a[2]); a[3] = fmaf(vv.z, w2.w, a[3]);
            a[0] = fmaf(vv.w, w3.x, a[0]); a[1] = fmaf(vv.w, w3.y, a[1]);
            a[2] = fmaf(vv.w, w3.z, a[2]); a[3] = fmaf(vv.w, w3.w, a[3]);
        }
    }
#pragma unroll
    for (int u = 0; u < 2; ++u) {
        const int j = wj + u * 6;
#pragma unroll
        for (int r = 0; r < 2; ++r)
            *reinterpret_cast<float4*>(ds + j * 512 + ks * 256 + r * 128 + gv * 4)
                = make_float4(acc[u][r][0], acc[u][r][1], acc[u][r][2], acc[u][r][3]);
    }
}

__global__ void __launch_bounds__(512, 1)
qru_main(const float* __restrict__ hx,
         float* __restrict__ out, float* __restrict__ hT, int writeHT)
{
    extern __shared__ float smf[];
    float* ds  = smf;             //  6144 : Gauss partials [j][ks][r][g]
    float* vB  = smf + 6144;      //  2048 : [r][slot(8)][128] (h-half | cand-half)
    float* yb  = smf + 8192;      //  1024
    float* Wsh = smf + 9216;      // 32768 : base W_hh [4][64][128]

    const int t   = threadIdx.x;
    const int b0  = blockIdx.x * 2;
    const int c   = t >> 7;            // combine component
    const int g   = t & 127;           // combine column
    const int w   = t >> 5;
    const int wj  = w >> 1;            // 0..7 (active < 6)
    const int ksD = w & 1;
    const int gv  = t & 31;
    const int rC  = t >> 6;            // t<128 epilogue row
    const int nC  = t & 63;

    for (int u = t; u < 32768; u += 512) Wsh[u] = g_WHH[u];

    float hc[4], hn[4], ct[4];
    if (t < 128) {
#pragma unroll
        for (int p = 0; p < 4; ++p)
            hc[p] = hx[(b0 + rC) * 256 + p * 64 + nC];
    }
    __syncthreads();

    const float* xk0p = g_XK + (size_t)b0 * 512 + t;

    for (int s = 0; s < 512; ++s) {
        const float* xkp = xk0p + (size_t)s * 256 * 512;
        float xk0 = xkp[0];
        float xk1 = xkp[512];

        // (a) normalize h (regs) -> vB h-half slots (4 comps + 4 combos)
        if (t < 128) {
            float m2 = hc[0]*hc[0] + hc[1]*hc[1] + hc[2]*hc[2] + hc[3]*hc[3];
            float inv = 1.f / (sqrtf(m2) + 1e-4f);
#pragma unroll
            for (int p = 0; p < 4; ++p) hn[p] = hc[p] * inv;
            float* vb = vB + rC * 1024 + nC;
            vb[0]   = hn[0];          vb[128] = hn[1];
            vb[256] = hn[2];          vb[384] = hn[3];
            vb[512] = hn[0] + hn[1];  vb[640] = hn[2] - hn[3];
            vb[768] = hn[2] + hn[3];  vb[896] = hn[0] - hn[1];
        }
        __syncthreads();

        // phase A Gauss dots
        if (w < 12) {
            if (wj == 2)      qdotA12(g_WA2,        vB, ds, 2, ksD, gv);
            else if (wj == 5) qdotA12(g_WA2 + 8192, vB, ds, 5, ksD, gv);
            else {
                int m = (wj < 2) ? wj : wj - 1;     // smem base index 0..3
                qdotA12(Wsh + m * 8192, vB, ds, wj, ksD, gv);
            }
        }
        __syncthreads();

        // combine A (Gauss recombination) + XK + bias
        {
            float xk[2] = {xk0, xk1};
#pragma unroll
            for (int r = 0; r < 2; ++r) {
                const float* dsr = ds + r * 128 + g;
#define DJ(j) (dsr[(j) * 512] + dsr[(j) * 512 + 256])
                float y = xk[r] + g_bA[c * 128 + g];
                if (c == 0)      y += DJ(0) - DJ(1) - DJ(3) - DJ(4);
                else if (c == 1) y += DJ(2) - DJ(0) - DJ(1) - DJ(5) + DJ(3) - DJ(4);
                else if (c == 2) y += DJ(6) - DJ(7) + DJ(9) + DJ(10);
                else             y += DJ(8) - DJ(6) - DJ(7) + DJ(11) - DJ(9) + DJ(10);
#undef DJ
                yb[r * 512 + c * 128 + g] = y;
            }
        }
        __syncthreads();

        // (e) amp gate + cand_t (regs) -> vB cand-half slots
        if (t < 128) {
            float a0 = yb[rC * 512 + nC],        a1 = yb[rC * 512 + 128 + nC];
            float a2 = yb[rC * 512 + 256 + nC],  a3 = yb[rC * 512 + 384 + nC];
            float ag = sqrtf(a0 * a0 + a1 * a1 + a2 * a2 + a3 * a3);
            float q0 = yb[rC * 512 + 64 + nC]  * ag;
            float q1 = yb[rC * 512 + 192 + nC] * ag;
            float q2 = yb[rC * 512 + 320 + nC] * ag;
            float q3 = yb[rC * 512 + 448 + nC] * ag;
            float inv = 1.f / (sqrtf(q0 * q0 + q1 * q1 + q2 * q2 + q3 * q3) + 1e-4f);
            ct[0] = q0 * inv; ct[1] = q1 * inv; ct[2] = q2 * inv; ct[3] = q3 * inv;
            float* vb = vB + rC * 1024 + 64 + nC;
            vb[0]   = ct[0];          vb[128] = ct[1];
            vb[256] = ct[2];          vb[384] = ct[3];
            vb[512] = ct[0] + ct[1];  vb[640] = ct[2] - ct[3];
            vb[768] = ct[2] + ct[3];  vb[896] = ct[0] - ct[1];
        }
        __syncthreads();

        // phase B Gauss dots
        if (w < 12) qdotB12(vB, ds, wj, ksD, gv);
        __syncthreads();

        // combine B (Gauss recombination)
#pragma unroll
        for (int r = 0; r < 2; ++r) {
            const float* dsr = ds + r * 128 + g;
#define DJ(j) (dsr[(j) * 512] + dsr[(j) * 512 + 256])
            float y = g_bB[c * 128 + g];
            if (c == 0)      y += DJ(0) - DJ(1) - DJ(3) - DJ(4);
            else if (c == 1) y += DJ(2) - DJ(0) - DJ(1) - DJ(5) + DJ(3) - DJ(4);
            else if (c == 2) y += DJ(6) - DJ(7) + DJ(9) + DJ(10);
            else             y += DJ(8) - DJ(6) - DJ(7) + DJ(11) - DJ(9) + DJ(10);
#undef DJ
            yb[r * 512 + c * 128 + g] = y;
        }
        __syncthreads();

        // (h) gates + state update (regs) + output
        if (t < 128) {
            float u0 = yb[rC * 512 + nC];
            float u2 = yb[rC * 512 + 128 + nC];
            float u4 = yb[rC * 512 + 256 + nC];
            float gh = sqrtf(u0 * u0 + 2.f * u2 * u2 + u4 * u4);   // faithful gate
            float u1 = yb[rC * 512 + 64 + nC],  u3 = yb[rC * 512 + 192 + nC];
            float u5 = yb[rC * 512 + 320 + nC], u7 = yb[rC * 512 + 448 + nC];
            float gc = sqrtf(u1 * u1 + u3 * u3 + u5 * u5 + u7 * u7);
            float* orow = out + (size_t)(s * 256 + b0 + rC) * 256;
#pragma unroll
            for (int p = 0; p < 4; ++p) {
                float av = fmaf(hn[p], gh, ct[p] * gc);
                hc[p] = av;
                orow[p * 64 + nC] = av;
            }
            if (writeHT && s == 511)
#pragma unroll
                for (int p = 0; p < 4; ++p)
                    hT[(size_t)(b0 + rC) * 256 + p * 64 + nC] = hc[p];
        }
        // no barrier: next (a) uses only this thread's hc; vB writers are the
        // same t<128 threads, and readers sit behind the post-(a) barrier.
    }
}

extern "C" void kernel_launch(void* const* d_in, const int* in_sizes, int n_in,
                              void* d_out, int out_size)
{
    const float* x  = (const float*)d_in[0];
    const float* hx = (const float*)d_in[1];

    qru_prep<<<1092, 256>>>(
        (const float*)d_in[2],  (const float*)d_in[3],  (const float*)d_in[4],  (const float*)d_in[5],
        (const float*)d_in[6],  (const float*)d_in[7],  (const float*)d_in[8],  (const float*)d_in[9],
        (const float*)d_in[10], (const float*)d_in[11], (const float*)d_in[12], (const float*)d_in[13],
        (const float*)d_in[14], (const float*)d_in[15], (const float*)d_in[16], (const float*)d_in[17],
        (const float*)d_in[18], (const float*)d_in[19], (const float*)d_in[20], (const float*)d_in[21]);

    size_t smx = 92160;
    cudaFuncSetAttribute(qru_xk, cudaFuncAttributeMaxDynamicSharedMemorySize, (int)smx);
    qru_xk<<<8192, 256, smx>>>(x);

    float* out = (float*)d_out;
    long long base = 512LL * 256 * 256;
    int writeHT = (out_size >= base + 256 * 256) ? 1 : 0;
    float* hT = out + base;

    size_t smm = 41984 * sizeof(float);                  // 167936 B
    cudaFuncSetAttribute(qru_main, cudaFuncAttributeMaxDynamicSharedMemorySize, (int)smm);
    qru_main<<<128, 512, smm>>>(hx, out, hT, writeHT);
}

// round 17
// speedup vs baseline: 1.3627x; 1.0567x over previous
#include <cuda_runtime.h>
#include <cuda_fp16.h>
#include <cstdint>

// QRU forward. R16:
//  - xk: fp16 HMMA scaled split, 4 passes (hh, hm, mh, mm~), 2 acc groups.
//  - main: Gauss 12-product both phases (R15); epilogue sections (a)/(e)/(h)
//    remapped to all 512 threads (thread = (r,n,comp), quad shfl.bfly moduli,
//    scalar register state); (h) merged with next-(a); padded vB/yb strides
//    (136) for conflict-free epilogue access.

__device__ float g_WHH[4 * 64 * 128];               // base A matrices [c][k][g]
__device__ float g_WA2[2 * 64 * 128];               // A combos {W0+W1, W2+W3}
__device__ float g_WB6[6 * 128 * 128];              // {W0,W1,W0+W1,W2,W3,W2+W3}
__device__ float g_bA[512];
__device__ float g_bB[512];
__device__ unsigned short g_B4[4ull * 512 * 256];   // K_ih^T fp16 h/m/m~ (t unused)
__device__ float g_XK[131072ull * 512];

__constant__ int   c_M[16] = {0,1,2,3,  1,0,3,2,  2,3,0,1,  3,2,1,0};
__constant__ float c_S[16] = {1.f,-1.f,-1.f,-1.f,  1.f,1.f,-1.f,1.f,
                              1.f,1.f,1.f,-1.f,    1.f,-1.f,1.f,1.f};
__constant__ int   c_SX[12] = {0,1,4,2,3,5,  2,3,6,0,1,7};

#define SPLIT_S  4.8828125e-4f      // 2^-11
#define SPLIT_U  2048.f             // 2^11
#define VBR 1088                    // vB r-stride (8 slots * 136)
#define VBS 136                     // vB slot stride (pad)
#define YBR 544                     // yb r-stride (4 comps * 136)
#define YBS 136                     // yb comp stride (pad)

// ---------------- prep ------------------------------------------------------
__global__ void qru_prep(
    const float* __restrict__ wih_r, const float* __restrict__ wih_i,
    const float* __restrict__ wih_j, const float* __restrict__ wih_k,
    const float* __restrict__ whh_r, const float* __restrict__ whh_i,
    const float* __restrict__ whh_j, const float* __restrict__ whh_k,
    const float* __restrict__ wpc_r, const float* __restrict__ wpc_i,
    const float* __restrict__ wpc_j, const float* __restrict__ wpc_k,
    const float* __restrict__ wph_r, const float* __restrict__ wph_i,
    const float* __restrict__ wph_j, const float* __restrict__ wph_k,
    const float* __restrict__ b_ih, const float* __restrict__ b_hh,
    const float* __restrict__ b_ph, const float* __restrict__ b_pc)
{
    int i = blockIdx.x * blockDim.x + threadIdx.x;
    if (i < 98304) {                       // g_WB6: [mat][k][g]
        int mat = i >> 14, k = (i >> 7) & 127, gg = i & 127;
        const float* s0;
        const float* s1 = 0;
        int kk = (k & 63) * 128 + gg;
        if (k < 64) {
            s0 = (mat == 0 || mat == 2) ? wph_r :
                 (mat == 1)             ? wph_i :
                 (mat == 3 || mat == 5) ? wph_j : wph_k;
            if (mat == 2) s1 = wph_i;
            if (mat == 5) s1 = wph_k;
        } else {
            s0 = (mat == 0 || mat == 2) ? wpc_r :
                 (mat == 1)             ? wpc_i :
                 (mat == 3 || mat == 5) ? wpc_j : wpc_k;
            if (mat == 2) s1 = wpc_i;
            if (mat == 5) s1 = wpc_k;
        }
        float v = s0[kk];
        if (s1) v += s1[kk];
        g_WB6[i] = v;
    } else if (i < 131072) {               // g_WHH (base A)
        int j = i - 98304;
        int cc = j >> 13, k = (j >> 7) & 63, gg = j & 127;
        const float* src = (cc == 0 ? whh_r : cc == 1 ? whh_i : cc == 2 ? whh_j : whh_k);
        g_WHH[j] = src[k * 128 + gg];
    } else if (i < 147456) {               // g_WA2 combos
        int j = i - 131072;
        int m2 = j >> 13, k = (j >> 7) & 63, gg = j & 127;
        const float* a = m2 ? whh_j : whh_r;
        const float* b = m2 ? whh_k : whh_i;
        g_WA2[j] = a[k * 128 + gg] + b[k * 128 + gg];
    } else if (i < 278528) {               // g_B4: K_ih^T scaled fp16 h/m/m~
        int j = i - 147456;                // j = n*256 + k
        int n = j >> 8, k = j & 255;
        int q = n >> 7, gg = n & 127, p = k >> 6, kq = k & 63;
        int cm = c_M[q * 4 + p];
        const float* src = (cm == 0 ? wih_r : cm == 1 ? wih_i : cm == 2 ? wih_j : wih_k);
        float val = c_S[q * 4 + p] * src[kq * 128 + gg];
        __half hh = __float2half_rn(val);
        float r1 = val - __half2float(hh);
        __half mm = __float2half_rn(r1 * SPLIT_U);
        g_B4[j]          = __half_as_ushort(hh);
        g_B4[131072 + j] = __half_as_ushort(mm);
        g_B4[262144 + j] = __half_as_ushort(__float2half_rn(__half2float(mm) * SPLIT_S));
    } else if (i < 279552) {
        int j = i - 278528;
        if (j < 512) g_bA[j] = b_ih[j] + b_hh[j];
        else         g_bB[j - 512] = b_ph[j - 512] + b_pc[j - 512];
    }
}

// ---------------- xk GEMM (4 passes) ----------------------------------------
__device__ __forceinline__ uint32_t s2u(const void* p) {
    uint32_t a;
    asm("{ .reg .u64 t; cvta.to.shared.u64 t, %1; cvt.u32.u64 %0, t; }" : "=r"(a) : "l"(p));
    return a;
}
#define MMAH(d, a, b0, b1)                                                     \
    asm volatile("mma.sync.aligned.m16n8k16.row.col.f32.f16.f16.f32 "          \
        "{%0,%1,%2,%3},{%4,%5,%6,%7},{%8,%9},{%0,%1,%2,%3};"                   \
        : "+f"((d)[0]), "+f"((d)[1]), "+f"((d)[2]), "+f"((d)[3])               \
        : "r"((a)[0]), "r"((a)[1]), "r"((a)[2]), "r"((a)[3]),                  \
          "r"(b0), "r"(b1))
#define LDSM4(r, addr)                                                         \
    asm volatile("ldmatrix.sync.aligned.m8n8.x4.shared.b16 {%0,%1,%2,%3}, [%4];" \
        : "=r"((r)[0]), "=r"((r)[1]), "=r"((r)[2]), "=r"((r)[3]) : "r"(addr))
#define LDSM2(r0, r1, addr)                                                    \
    asm volatile("ldmatrix.sync.aligned.m8n8.x2.shared.b16 {%0,%1}, [%2];"     \
        : "=r"(r0), "=r"(r1) : "r"(addr))

// SMEM: A terms h/m: [128][72]ush at 0, 9216 (18432B each);
//       B terms h/m/m~: [64][72]ush at 18432 + T*4608 ush.  64512 B total.
__global__ void __launch_bounds__(256, 2)
qru_xk(const float* __restrict__ x)
{
    extern __shared__ unsigned short smu[];
    const uint32_t smb = s2u(smu);
    const int t = threadIdx.x;
    const int mt = blockIdx.x >> 3, nt = blockIdx.x & 7;
    const int n0 = nt * 64;
    const int lane = t & 31, w = t >> 5;
    const int wm = w >> 1, wn = w & 1;
    const int gq = lane >> 2, tg = lane & 3;

    const uint32_t aRow = (uint32_t)((lane & 15) * 144 + (lane >> 4) * 16);
    const uint32_t bRow = (uint32_t)((lane & 7) * 144 + ((lane >> 3) & 1) * 16);

    float acc[2][2][4][4];
#pragma unroll
    for (int g = 0; g < 2; ++g)
#pragma unroll
        for (int f = 0; f < 2; ++f)
#pragma unroll
            for (int nf = 0; nf < 4; ++nf)
#pragma unroll
                for (int i = 0; i < 4; ++i) acc[g][f][nf][i] = 0.f;

    const int pa[4] = {0, 0, 1, 1};        // A term: h,h,m,m
    const int pb[4] = {0, 1, 0, 2};        // B term: h,m,h,m~
    const int pg[4] = {0, 1, 1, 1};

    for (int kc = 0; kc < 4; ++kc) {
        // A fill: 2-term split
        for (int u = t; u < 2048; u += 256) {
            int row = u >> 4, q4 = u & 15;
            float4 a = ((const float4*)x)[(size_t)(mt * 128 + row) * 64 + kc * 16 + q4];
            float v[4] = {a.x, a.y, a.z, a.w};
            unsigned short H[4], M[4];
#pragma unroll
            for (int e = 0; e < 4; ++e) {
                __half hh = __float2half_rn(v[e]);
                H[e] = __half_as_ushort(hh);
                M[e] = __half_as_ushort(__float2half_rn((v[e] - __half2float(hh)) * SPLIT_U));
            }
            uint32_t* pH = (uint32_t*)(smu + row * 72 + q4 * 4);
            uint32_t* pM = (uint32_t*)(smu + 9216 + row * 72 + q4 * 4);
            pH[0] = (uint32_t)H[0] | ((uint32_t)H[1] << 16);
            pH[1] = (uint32_t)H[2] | ((uint32_t)H[3] << 16);
            pM[0] = (uint32_t)M[0] | ((uint32_t)M[1] << 16);
            pM[1] = (uint32_t)M[2] | ((uint32_t)M[3] << 16);
        }
        // B fill: 3 terms x 64 n x 8 x 16B
        for (int u = t; u < 1536; u += 256) {
            int T4 = u >> 9, v = u & 511, n = v >> 3, kx = v & 7;
            *(uint4*)(smu + 18432 + T4 * 4608 + n * 72 + kx * 8) =
                *(const uint4*)(g_B4 + (size_t)T4 * 131072
                                + (size_t)(n0 + n) * 256 + kc * 64 + kx * 8);
        }
        __syncthreads();

#pragma unroll
        for (int ps = 0; ps < 4; ++ps) {
            const uint32_t uA = smb + pa[ps] * 18432 + wm * 4608 + aRow;
            const uint32_t uB = smb + 36864 + pb[ps] * 9216 + wn * 4608 + bRow;
            float* g0 = &acc[pg[ps]][0][0][0];
            float* g1 = &acc[pg[ps]][1][0][0];
#pragma unroll
            for (int ks = 0; ks < 4; ++ks) {
                const uint32_t k0b = ks * 32;
                uint32_t af[4], ag[4];
                LDSM4(af, uA + k0b);
                LDSM4(ag, uA + 2304 + k0b);
#pragma unroll
                for (int nf = 0; nf < 4; ++nf) {
                    uint32_t b0, b1;
                    LDSM2(b0, b1, uB + nf * 1152 + k0b);
                    MMAH(g0 + nf * 4, af, b0, b1);
                    MMAH(g1 + nf * 4, ag, b0, b1);
                }
            }
        }
        __syncthreads();
    }

#pragma unroll
    for (int f = 0; f < 2; ++f)
#pragma unroll
        for (int nf = 0; nf < 4; ++nf) {
            float v0[4];
#pragma unroll
            for (int i = 0; i < 4; ++i)
                v0[i] = acc[0][f][nf][i] + SPLIT_S * acc[1][f][nf][i];
            int row = mt * 128 + wm * 32 + f * 16 + gq;
            int col = n0 + wn * 32 + nf * 8 + 2 * tg;
            *(float2*)&g_XK[(size_t)row * 512 + col]       = make_float2(v0[0], v0[1]);
            *(float2*)&g_XK[(size_t)(row + 8) * 512 + col] = make_float2(v0[2], v0[3]);
        }
}

// ---------------- recurrent kernel ------------------------------------------
__device__ __forceinline__ void qdotA12(const float* __restrict__ W,
                                        const float* __restrict__ vB,
                                        float* __restrict__ ds,
                                        int wj, int ks, int gv)
{
    const int s0 = c_SX[wj], s1 = c_SX[wj + 6];
    float acc[2][2][4];
#pragma unroll
    for (int u = 0; u < 2; ++u)
#pragma unroll
        for (int r = 0; r < 2; ++r)
#pragma unroll
            for (int i = 0; i < 4; ++i) acc[u][r][i] = 0.f;

    const float4* Wp = reinterpret_cast<const float4*>(W) + (ks * 32) * 32 + gv;
    const float* v00 = vB + 0 * VBR + s0 * VBS + ks * 32;
    const float* v01 = vB + 1 * VBR + s0 * VBS + ks * 32;
    const float* v10 = vB + 0 * VBR + s1 * VBS + ks * 32;
    const float* v11 = vB + 1 * VBR + s1 * VBS + ks * 32;

#pragma unroll 2
    for (int kb = 0; kb < 32; kb += 4) {
        float4 w0 = Wp[0], w1 = Wp[32], w2 = Wp[64], w3 = Wp[96];
        Wp += 128;
#pragma unroll
        for (int st = 0; st < 4; ++st) {
            const float* vp = (st == 0) ? v00 : (st == 1) ? v01 : (st == 2) ? v10 : v11;
            const float4 vv = *reinterpret_cast<const float4*>(vp + kb);
            float* a = acc[st >> 1][st & 1];
            a[0] = fmaf(vv.x, w0.x, a[0]); a[1] = fmaf(vv.x, w0.y, a[1]);
            a[2] = fmaf(vv.x, w0.z, a[2]); a[3] = fmaf(vv.x, w0.w, a[3]);
            a[0] = fmaf(vv.y, w1.x, a[0]); a[1] = fmaf(vv.y, w1.y, a[1]);
            a[2] = fmaf(vv.y, w1.z, a[2]); a[3] = fmaf(vv.y, w1.w, a[3]);
            a[0] = fmaf(vv.z, w2.x, a[0]); a[1] = fmaf(vv.z, w2.y, a[1]);
            a[2] = fmaf(vv.z, w2.z, a[2]); a[3] = fmaf(vv.z, w2.w, a[3]);
            a[0] = fmaf(vv.w, w3.x, a[0]); a[1] = fmaf(vv.w, w3.y, a[1]);
            a[2] = fmaf(vv.w, w3.z, a[2]); a[3] = fmaf(vv.w, w3.w, a[3]);
        }
    }
#pragma unroll
    for (int u = 0; u < 2; ++u) {
        const int j = wj + u * 6;
#pragma unroll
        for (int r = 0; r < 2; ++r)
            *reinterpret_cast<float4*>(ds + j * 512 + ks * 256 + r * 128 + gv * 4)
                = make_float4(acc[u][r][0], acc[u][r][1], acc[u][r][2], acc[u][r][3]);
    }
}

__device__ __forceinline__ void qdotB12(const float* __restrict__ vB,
                                        float* __restrict__ ds,
                                        int wj, int ks, int gv)
{
    const int s0 = c_SX[wj], s1 = c_SX[wj + 6];
    float acc[2][2][4];
#pragma unroll
    for (int u = 0; u < 2; ++u)
#pragma unroll
        for (int r = 0; r < 2; ++r)
#pragma unroll
            for (int i = 0; i < 4; ++i) acc[u][r][i] = 0.f;

    const float4* Wp = reinterpret_cast<const float4*>(g_WB6) + (wj * 128 + ks * 64) * 32 + gv;
    const float* v00 = vB + 0 * VBR + s0 * VBS + ks * 64;
    const float* v01 = vB + 1 * VBR + s0 * VBS + ks * 64;
    const float* v10 = vB + 0 * VBR + s1 * VBS + ks * 64;
    const float* v11 = vB + 1 * VBR + s1 * VBS + ks * 64;

#pragma unroll 2
    for (int kb = 0; kb < 64; kb += 4) {
        float4 w0 = Wp[0], w1 = Wp[32], w2 = Wp[64], w3 = Wp[96];
        Wp += 128;
#pragma unroll
        for (int st = 0; st < 4; ++st) {
            const float* vp = (st == 0) ? v00 : (st == 1) ? v01 : (st == 2) ? v10 : v11;
            const float4 vv = *reinterpret_cast<const float4*>(vp + kb);
            float* a = acc[st >> 1][st & 1];
            a[0] = fmaf(vv.x, w0.x, a[0]); a[1] = fmaf(vv.x, w0.y, a[1]);
            a[2] = fmaf(vv.x, w0.z, a[2]); a[3] = fmaf(vv.x, w0.w, a[3]);
            a[0] = fmaf(vv.y, w1.x, a[0]); a[1] = fmaf(vv.y, w1.y, a[1]);
            a[2] = fmaf(vv.y, w1.z, a[2]); a[3] = fmaf(vv.y, w1.w, a[3]);
            a[0] = fmaf(vv.z, w2.x, a[0]); a[1] = fmaf(vv.z, w2.y, a[1]);
            a[2] = fmaf(vv.z, w2.z, a[2]); a[3] = fmaf(vv.z, w2.w, a[3]);
            a[0] = fmaf(vv.w, w3.x, a[0]); a[1] = fmaf(vv.w, w3.y, a[1]);
            a[2] = fmaf(vv.w, w3.z, a[2]); a[3] = fmaf(vv.w, w3.w, a[3]);
        }
    }
#pragma unroll
    for (int u = 0; u < 2; ++u) {
        const int j = wj + u * 6;
#pragma unroll
        for (int r = 0; r < 2; ++r)
            *reinterpret_cast<float4*>(ds + j * 512 + ks * 256 + r * 128 + gv * 4)
                = make_float4(acc[u][r][0], acc[u][r][1], acc[u][r][2], acc[u][r][3]);
    }
}

__global__ void __launch_bounds__(512, 1)
qru_main(const float* __restrict__ hx,
         float* __restrict__ out, float* __restrict__ hT, int writeHT)
{
    extern __shared__ float smf[];
    float* ds  = smf;             //  6144 : Gauss partials [j][ks][r][g]
    float* vB  = smf + 6144;      //  2176 : [r][slot(8)][136]
    float* yb  = smf + 8320;      //  1088 : [r][comp(4)][136]
    float* Wsh = smf + 9408;      // 32768 : base W_hh [4][64][128]

    const int t   = threadIdx.x;
    const int b0  = blockIdx.x * 2;
    const int cCb = t >> 7;            // combine comp
    const int gCb = t & 127;           // combine column
    const int w   = t >> 5;
    const int wj  = w >> 1;
    const int ksD = w & 1;
    const int gv  = t & 31;
    const int rE  = t >> 8;            // epilogue map: (r, n, comp)
    const int nE  = (t >> 2) & 63;
    const int cE  = t & 3;
    const int comboSlot = (cE == 0) ? 4 : (cE == 1) ? 7 : (cE == 2) ? 6 : 5;
    const float wgt = (cE == 1) ? 2.f : ((cE == 3) ? 0.f : 1.f);   // faithful gate

    for (int u = t; u < 32768; u += 512) Wsh[u] = g_WHH[u];

    float hc = hx[(b0 + rE) * 256 + cE * 64 + nE];
    float hn, ct = 0.f;

    // pre-loop (a): normalize + write vB h-half
    {
        float m2 = hc * hc;
        m2 += __shfl_xor_sync(0xFFFFFFFFu, m2, 1);
        m2 += __shfl_xor_sync(0xFFFFFFFFu, m2, 2);
        hn = hc * (1.f / (sqrtf(m2) + 1e-4f));
        vB[rE * VBR + cE * VBS + nE] = hn;
        float other = __shfl_xor_sync(0xFFFFFFFFu, hn, 1);
        vB[rE * VBR + comboSlot * VBS + nE] = (cE & 1) ? (other - hn) : (hn + other);
    }
    __syncthreads();

    const float* xk0p = g_XK + (size_t)b0 * 512 + t;

    for (int s = 0; s < 512; ++s) {
        const float* xkp = xk0p + (size_t)s * 131072;
        float xk0 = xkp[0];
        float xk1 = xkp[512];

        // phase A Gauss dots
        if (w < 12) {
            if (wj == 2)      qdotA12(g_WA2,        vB, ds, 2, ksD, gv);
            else if (wj == 5) qdotA12(g_WA2 + 8192, vB, ds, 5, ksD, gv);
            else {
                int m = (wj < 2) ? wj : wj - 1;
                qdotA12(Wsh + m * 8192, vB, ds, wj, ksD, gv);
            }
        }
        __syncthreads();

        // combine A + XK + bias -> yb
        {
            float xk[2] = {xk0, xk1};
#pragma unroll
            for (int r = 0; r < 2; ++r) {
                const float* dsr = ds + r * 128 + gCb;
#define DJ(j) (dsr[(j) * 512] + dsr[(j) * 512 + 256])
                float y = xk[r] + g_bA[cCb * 128 + gCb];
                if (cCb == 0)      y += DJ(0) - DJ(1) - DJ(3) - DJ(4);
                else if (cCb == 1) y += DJ(2) - DJ(0) - DJ(1) - DJ(5) + DJ(3) - DJ(4);
                else if (cCb == 2) y += DJ(6) - DJ(7) + DJ(9) + DJ(10);
                else               y += DJ(8) - DJ(6) - DJ(7) + DJ(11) - DJ(9) + DJ(10);
#undef DJ
                yb[r * YBR + cCb * YBS + gCb] = y;
            }
        }
        __syncthreads();

        // (e) amp gate + cand_t, full-width (r,n,comp)
        {
            float aC = yb[rE * YBR + cE * YBS + nE];
            float qC = yb[rE * YBR + cE * YBS + 64 + nE];
            float as = aC * aC;
            as += __shfl_xor_sync(0xFFFFFFFFu, as, 1);
            as += __shfl_xor_sync(0xFFFFFFFFu, as, 2);
            float qv = qC * sqrtf(as);
            float qs = qv * qv;
            qs += __shfl_xor_sync(0xFFFFFFFFu, qs, 1);
            qs += __shfl_xor_sync(0xFFFFFFFFu, qs, 2);
            ct = qv * (1.f / (sqrtf(qs) + 1e-4f));
            vB[rE * VBR + cE * VBS + 64 + nE] = ct;
            float other = __shfl_xor_sync(0xFFFFFFFFu, ct, 1);
            vB[rE * VBR + comboSlot * VBS + 64 + nE] = (cE & 1) ? (other - ct) : (ct + other);
        }
        __syncthreads();

        // phase B Gauss dots
        if (w < 12) qdotB12(vB, ds, wj, ksD, gv);
        __syncthreads();

        // combine B -> yb
#pragma unroll
        for (int r = 0; r < 2; ++r) {
            const float* dsr = ds + r * 128 + gCb;
#define DJ(j) (dsr[(j) * 512] + dsr[(j) * 512 + 256])
            float y = g_bB[cCb * 128 + gCb];
            if (cCb == 0)      y += DJ(0) - DJ(1) - DJ(3) - DJ(4);
            else if (cCb == 1) y += DJ(2) - DJ(0) - DJ(1) - DJ(5) + DJ(3) - DJ(4);
            else if (cCb == 2) y += DJ(6) - DJ(7) + DJ(9) + DJ(10);
            else               y += DJ(8) - DJ(6) - DJ(7) + DJ(11) - DJ(9) + DJ(10);
#undef DJ
            yb[r * YBR + cCb * YBS + gCb] = y;
        }
        __syncthreads();

        // (h)+(a): gates, state update, output, normalize for next step
        {
            float uH = yb[rE * YBR + cE * YBS + nE];
            float uC = yb[rE * YBR + cE * YBS + 64 + nE];
            float hs = wgt * uH * uH;
            hs += __shfl_xor_sync(0xFFFFFFFFu, hs, 1);
            hs += __shfl_xor_sync(0xFFFFFFFFu, hs, 2);
            float cs = uC * uC;
            cs += __shfl_xor_sync(0xFFFFFFFFu, cs, 1);
            cs += __shfl_xor_sync(0xFFFFFFFFu, cs, 2);
            float av = fmaf(hn, sqrtf(hs), ct * sqrtf(cs));
            out[(size_t)(s * 256 + b0 + rE) * 256 + cE * 64 + nE] = av;
            if (writeHT && s == 511)
                hT[(size_t)(b0 + rE) * 256 + cE * 64 + nE] = av;
            hc = av;
            float m2 = av * av;
            m2 += __shfl_xor_sync(0xFFFFFFFFu, m2, 1);
            m2 += __shfl_xor_sync(0xFFFFFFFFu, m2, 2);
            hn = av * (1.f / (sqrtf(m2) + 1e-4f));
            vB[rE * VBR + cE * VBS + nE] = hn;
            float other = __shfl_xor_sync(0xFFFFFFFFu, hn, 1);
            vB[rE * VBR + comboSlot * VBS + nE] = (cE & 1) ? (other - hn) : (hn + other);
        }
        __syncthreads();
    }
}

extern "C" void kernel_launch(void* const* d_in, const int* in_sizes, int n_in,
                              void* d_out, int out_size)
{
    const float* x  = (const float*)d_in[0];
    const float* hx = (const float*)d_in[1];

    qru_prep<<<1092, 256>>>(
        (const float*)d_in[2],  (const float*)d_in[3],  (const float*)d_in[4],  (const float*)d_in[5],
        (const float*)d_in[6],  (const float*)d_in[7],  (const float*)d_in[8],  (const float*)d_in[9],
        (const float*)d_in[10], (const float*)d_in[11], (const float*)d_in[12], (const float*)d_in[13],
        (const float*)d_in[14], (const float*)d_in[15], (const float*)d_in[16], (const float*)d_in[17],
        (const float*)d_in[18], (const float*)d_in[19], (const float*)d_in[20], (const float*)d_in[21]);

    size_t smx = 64512;                                  // bytes
    cudaFuncSetAttribute(qru_xk, cudaFuncAttributeMaxDynamicSharedMemorySize, (int)smx);
    qru_xk<<<8192, 256, smx>>>(x);

    float* out = (float*)d_out;
    long long base = 512LL * 256 * 256;
    int writeHT = (out_size >= base + 256 * 256) ? 1 : 0;
    float* hT = out + base;

    size_t smm = 42176 * sizeof(float);                  // 168704 B
    cudaFuncSetAttribute(qru_main, cudaFuncAttributeMaxDynamicSharedMemorySize, (int)smm);
    qru_main<<<128, 512, smm>>>(hx, out, hT, writeHT);
}